// round 11
// baseline (speedup 1.0000x reference)
#include <cuda_runtime.h>
#include <cuda_bf16.h>
#include <cuda_fp16.h>
#include <cstdint>
#include <cstring>

#define EPS 1e-5f
typedef unsigned long long u64;

// ---------------- f32x2 packed helpers ----------------
__device__ __forceinline__ u64 pk2(float lo, float hi) {
    u64 r;
    asm("mov.b64 %0, {%1, %2};" : "=l"(r) : "f"(lo), "f"(hi));
    return r;
}
__device__ __forceinline__ void upk2(u64 v, float& lo, float& hi) {
    asm("mov.b64 {%0, %1}, %2;" : "=f"(lo), "=f"(hi) : "l"(v));
}
__device__ __forceinline__ u64 ffma2_(u64 a, u64 b, u64 c) {
    u64 d;
    asm("fma.rn.f32x2 %0, %1, %2, %3;" : "=l"(d) : "l"(a), "l"(b), "l"(c));
    return d;
}
__device__ __forceinline__ __half2 u2h(uint32_t u) {
    __half2 h;
    memcpy(&h, &u, 4);
    return h;
}

// ---------------- cp.async helpers ----------------
__device__ __forceinline__ void cp16(void* smem_dst, const void* gsrc) {
    unsigned s = (unsigned)__cvta_generic_to_shared(smem_dst);
    asm volatile("cp.async.cg.shared.global [%0], [%1], 16;" :: "r"(s), "l"(gsrc));
}
__device__ __forceinline__ void cp_commit() {
    asm volatile("cp.async.commit_group;");
}
template <int N>
__device__ __forceinline__ void cp_wait() {
    asm volatile("cp.async.wait_group %0;" :: "n"(N));
}

// ---------------- mma helpers ----------------
__device__ __forceinline__ uint32_t smem_u32(const void* p) {
    uint32_t a;
    asm("{ .reg .u64 t; cvta.to.shared.u64 t, %1; cvt.u32.u64 %0, t; }" : "=r"(a) : "l"(p));
    return a;
}
__device__ __forceinline__ void ldsm4(uint32_t& r0, uint32_t& r1, uint32_t& r2, uint32_t& r3,
                                      uint32_t addr) {
    asm volatile("ldmatrix.sync.aligned.m8n8.x4.shared.b16 {%0,%1,%2,%3}, [%4];"
                 : "=r"(r0), "=r"(r1), "=r"(r2), "=r"(r3) : "r"(addr));
}
__device__ __forceinline__ void mma_f16(float* d, const uint32_t* a, uint32_t b0, uint32_t b1) {
    asm volatile(
        "mma.sync.aligned.m16n8k16.row.col.f32.f16.f16.f32 "
        "{%0,%1,%2,%3}, {%4,%5,%6,%7}, {%8,%9}, {%0,%1,%2,%3};"
        : "+f"(d[0]), "+f"(d[1]), "+f"(d[2]), "+f"(d[3])
        : "r"(a[0]), "r"(a[1]), "r"(a[2]), "r"(a[3]), "r"(b0), "r"(b1));
}

// ---------------- scratch ----------------
__device__ __half g_x_h[4 * 64 * 64 * 256];      // [b][h][w][c] fp16
__device__ int4   g_off4[4 * 9 * 64 * 64];       // corner elem offsets (half units)
__device__ uint4  g_cwh[4 * 9 * 64 * 64];        // 4 duplicated half2 corner weights
__device__ float  g_bias[256];
__device__ __align__(16) float2 g_dwp[9][128];   // [tap][ch-pair] depthwise weights
__device__ __half g_whi[256 * 256];              // [o][c] fp16 hi
__device__ __half g_wlo[256 * 256];              // [o][c] fp16 lo (residual)
__device__ __half g_mid[16384 * 256];            // [px][c] fp16 mid

// ---------------- kernel 1: NCHW fp32 -> NHWC fp16 ----------------
__global__ void k_transpose(const float* __restrict__ x) {
    __shared__ float tile[32][33];
    int b  = blockIdx.z;
    int s0 = blockIdx.x * 32;
    int c0 = blockIdx.y * 32;
    int tx = threadIdx.x, ty = threadIdx.y;  // (32, 8)
    const float* xb = x + (size_t)b * 256 * 4096;
    __half* ob = g_x_h + (size_t)b * 4096 * 256;
#pragma unroll
    for (int i = 0; i < 32; i += 8)
        tile[ty + i][tx] = xb[(c0 + ty + i) * 4096 + s0 + tx];
    __syncthreads();
    int tid = ty * 32 + tx;
#pragma unroll
    for (int j = 0; j < 2; j++) {
        int it = tid + j * 256;
        int r  = it >> 4, pc = it & 15;
        __half2 v = __floats2half2_rn(tile[pc * 2][r], tile[pc * 2 + 1][r]);
        *(__half2*)(ob + (size_t)(s0 + r) * 256 + c0 + pc * 2) = v;
    }
}

// ---------------- kernel 2: weight prep ----------------
__global__ void k_prep(const float* __restrict__ pw, const float* __restrict__ bg,
                       const float* __restrict__ bb, const float* __restrict__ bm,
                       const float* __restrict__ bv, const float* __restrict__ dw) {
    int idx = blockIdx.x * 256 + threadIdx.x;   // 65536 total
    int c = idx & 255;
    int o = idx >> 8;
    float s = bg[o] * rsqrtf(bv[o] + EPS);
    float w = __ldg(pw + o * 256 + c) * s;
    __half hi = __float2half_rn(w);
    __half lo = __float2half_rn(w - __half2float(hi));
    g_whi[o * 256 + c] = hi;
    g_wlo[o * 256 + c] = lo;
    if (idx < 256) {
        float s2 = bg[idx] * rsqrtf(bv[idx] + EPS);
        g_bias[idx] = bb[idx] - bm[idx] * s2;
    }
    if (idx < 9 * 128) {
        int k  = idx / 128;
        int cp = idx & 127;
        g_dwp[k][cp] = make_float2(__ldg(dw + (2 * cp) * 9 + k),
                                   __ldg(dw + (2 * cp + 1) * 9 + k));
    }
}

// ---------------- kernel 3: offset conv + sampling params (4-way group split) ----------------
// block = 256 = (w 64, gs 4); each gs slice handles 16 groups; smem tree-reduce.
__global__ __launch_bounds__(256) void k_offset(const float* __restrict__ gf,
                         const float* __restrict__ offw,
                         const float* __restrict__ og, const float* __restrict__ obt,
                         const float* __restrict__ om, const float* __restrict__ ov) {
    __shared__ __align__(16) char sbuf[46080];   // weights [9][64][10] f2, then partials
    float2 (*s_w2)[64][10] = (float2(*)[64][10])sbuf;
    float2 (*s_red)[64][9] = (float2(*)[64][9])sbuf;   // overlay after weights done

    int bh = blockIdx.x;
    int b = bh >> 6, h = bh & 63;
    int tid = threadIdx.x;
    int w  = tid & 63;
    int gs = tid >> 6;    // 0..3

    for (int i = tid; i < 9 * 64 * 9; i += 256) {
        int t = i % 9;
        int g = (i / 9) & 63;
        int k = i / 576;
        float wdy = offw[(2 * k) * 576 + g * 9 + t];
        float wdx = offw[(2 * k + 1) * 576 + g * 9 + t];
        s_w2[k][g][t] = make_float2(wdy, wdx);
    }
    __syncthreads();

    u64 acc[9];
#pragma unroll
    for (int k = 0; k < 9; k++) acc[k] = 0ull;

    const float* gfb = gf + (size_t)b * 64 * 64 * 64;
    int g0 = gs * 16;
    for (int gi = 0; gi < 16; gi++) {
        int g = g0 + gi;
        float a[9];
#pragma unroll
        for (int r = 0; r < 3; r++) {
            int hh = h + r - 1;
            bool hv = (unsigned)hh < 64u;
#pragma unroll
            for (int q = 0; q < 3; q++) {
                int ww = w + q - 1;
                bool wv2 = (unsigned)ww < 64u;
                a[r * 3 + q] = (hv && wv2) ? __ldg(gfb + (g * 64 + hh) * 64 + ww) : 0.f;
            }
        }
        u64 a2[9];
#pragma unroll
        for (int t = 0; t < 9; t++) a2[t] = pk2(a[t], a[t]);
#pragma unroll
        for (int k = 0; k < 9; k++) {
            const u64* wr = (const u64*)&s_w2[k][g][0];
            ulonglong2 w01 = *(const ulonglong2*)(wr + 0);
            ulonglong2 w23 = *(const ulonglong2*)(wr + 2);
            ulonglong2 w45 = *(const ulonglong2*)(wr + 4);
            ulonglong2 w67 = *(const ulonglong2*)(wr + 6);
            u64 w8 = wr[8];
            acc[k] = ffma2_(w01.x, a2[0], acc[k]);
            acc[k] = ffma2_(w01.y, a2[1], acc[k]);
            acc[k] = ffma2_(w23.x, a2[2], acc[k]);
            acc[k] = ffma2_(w23.y, a2[3], acc[k]);
            acc[k] = ffma2_(w45.x, a2[4], acc[k]);
            acc[k] = ffma2_(w45.y, a2[5], acc[k]);
            acc[k] = ffma2_(w67.x, a2[6], acc[k]);
            acc[k] = ffma2_(w67.y, a2[7], acc[k]);
            acc[k] = ffma2_(w8,    a2[8], acc[k]);
        }
    }

    // tree reduction across the 4 group-slices (overlay weight buffer)
    __syncthreads();
#pragma unroll
    for (int k = 0; k < 9; k++) {
        float lo, hi;
        upk2(acc[k], lo, hi);
        s_red[gs][w][k] = make_float2(lo, hi);
    }
    __syncthreads();
    if (gs != 0) return;

#pragma unroll
    for (int k = 0; k < 9; k++) {
        float2 p0 = s_red[0][w][k];
        float2 p1 = s_red[1][w][k];
        float2 p2 = s_red[2][w][k];
        float2 p3 = s_red[3][w][k];
        float dyr = (p0.x + p1.x) + (p2.x + p3.x);
        float dxr = (p0.y + p1.y) + (p2.y + p3.y);

        int j0 = 2 * k, j1 = 2 * k + 1;
        float s0 = og[j0] * rsqrtf(ov[j0] + EPS);
        float s1 = og[j1] * rsqrtf(ov[j1] + EPS);
        float dy = fmaxf((dyr - om[j0]) * s0 + obt[j0], 0.f);
        float dx = fmaxf((dxr - om[j1]) * s1 + obt[j1], 0.f);
        float ky = (float)((k / 3) - 1) * 2.0f;   // DIL = 2
        float kx = (float)((k % 3) - 1) * 2.0f;
        float gy = (float)h + ky + dy;
        float gx = (float)w + kx + dx;
        float y0f = floorf(gy), x0f = floorf(gx);
        float wy = gy - y0f, wx = gx - x0f;
        float omwy = 1.f - wy, omwx = 1.f - wx;
        int y0 = (int)y0f, x0 = (int)x0f;
        bool yv0 = (unsigned)y0 < 64u;
        bool yv1 = (unsigned)(y0 + 1) < 64u;
        bool xv0 = (unsigned)x0 < 64u;
        bool xv1 = (unsigned)(x0 + 1) < 64u;
        int y0c = min(max(y0, 0), 63);
        int y1c = min(max(y0 + 1, 0), 63);
        int x0c = min(max(x0, 0), 63);
        int x1c = min(max(x0 + 1, 0), 63);
        int idx = ((b * 9 + k) * 64 + h) * 64 + w;
        g_off4[idx] = make_int4((y0c * 64 + x0c) * 256, (y0c * 64 + x1c) * 256,
                                (y1c * 64 + x0c) * 256, (y1c * 64 + x1c) * 256);
        float c00 = omwy * omwx * (float)(yv0 && xv0);
        float c01 = omwy * wx   * (float)(yv0 && xv1);
        float c10 = wy * omwx   * (float)(yv1 && xv0);
        float c11 = wy * wx     * (float)(yv1 && xv1);
        __half2 h00 = __float2half2_rn(c00);
        __half2 h01 = __float2half2_rn(c01);
        __half2 h10 = __float2half2_rn(c10);
        __half2 h11 = __float2half2_rn(c11);
        uint4 pack;
        memcpy(&pack.x, &h00, 4);
        memcpy(&pack.y, &h01, 4);
        memcpy(&pack.z, &h10, 4);
        memcpy(&pack.w, &h11, 4);
        g_cwh[idx] = pack;
    }
}

// ---------------- kernel 4: fp16 sample + depthwise (one batch) ----------------
__global__ __launch_bounds__(256, 3) void k_sample(int b) {
    __shared__ __align__(16) int4 s_off[9][16];
    __shared__ __align__(16) uint4 s_cwh[9][16];

    int t  = blockIdx.x;          // 0..255 within batch
    int w0 = (t & 3) << 4;
    int h  = t >> 2;
    int tid = threadIdx.x;

    if (tid < 144) {
        int k = tid / 16, p = tid & 15;
        int idx = ((b * 9 + k) * 64 + h) * 64 + w0 + p;
        s_off[k][p] = g_off4[idx];
        s_cwh[k][p] = g_cwh[idx];
    }

    int cg = tid & 31;        // lane: 8 channels, c = cg*8
    int ps = tid >> 5;        // warp id: pixels ps*2, ps*2+1
    int c  = cg << 3;
    __syncthreads();

    const __half* xh = g_x_h + (size_t)b * 4096 * 256 + c;
    int pgbase = b * 4096 + h * 64 + w0;

    u64 acc[2][4];
#pragma unroll
    for (int i = 0; i < 2; i++)
#pragma unroll
        for (int j = 0; j < 4; j++) acc[i][j] = 0ull;

#pragma unroll
    for (int k = 0; k < 9; k++) {
        ulonglong2 dwA = *(const ulonglong2*)&g_dwp[k][cg * 4];
        ulonglong2 dwB = *(const ulonglong2*)&g_dwp[k][cg * 4 + 2];
#pragma unroll
        for (int i = 0; i < 2; i++) {
            int p = ps * 2 + i;
            int4 o4 = s_off[k][p];
            uint4 r00 = __ldg((const uint4*)(xh + o4.x));
            uint4 r01 = __ldg((const uint4*)(xh + o4.y));
            uint4 r10 = __ldg((const uint4*)(xh + o4.z));
            uint4 r11 = __ldg((const uint4*)(xh + o4.w));
            uint4 cw = s_cwh[k][p];
            __half2 w00 = u2h(cw.x), w01 = u2h(cw.y), w10 = u2h(cw.z), w11 = u2h(cw.w);
            __half2 v0 = __hmul2(w00, u2h(r00.x));
            __half2 v1 = __hmul2(w00, u2h(r00.y));
            __half2 v2 = __hmul2(w00, u2h(r00.z));
            __half2 v3 = __hmul2(w00, u2h(r00.w));
            v0 = __hfma2(w01, u2h(r01.x), v0);
            v1 = __hfma2(w01, u2h(r01.y), v1);
            v2 = __hfma2(w01, u2h(r01.z), v2);
            v3 = __hfma2(w01, u2h(r01.w), v3);
            v0 = __hfma2(w10, u2h(r10.x), v0);
            v1 = __hfma2(w10, u2h(r10.y), v1);
            v2 = __hfma2(w10, u2h(r10.z), v2);
            v3 = __hfma2(w10, u2h(r10.w), v3);
            v0 = __hfma2(w11, u2h(r11.x), v0);
            v1 = __hfma2(w11, u2h(r11.y), v1);
            v2 = __hfma2(w11, u2h(r11.z), v2);
            v3 = __hfma2(w11, u2h(r11.w), v3);
            float2 f0 = __half22float2(v0);
            float2 f1 = __half22float2(v1);
            float2 f2 = __half22float2(v2);
            float2 f3 = __half22float2(v3);
            acc[i][0] = ffma2_(dwA.x, pk2(f0.x, f0.y), acc[i][0]);
            acc[i][1] = ffma2_(dwA.y, pk2(f1.x, f1.y), acc[i][1]);
            acc[i][2] = ffma2_(dwB.x, pk2(f2.x, f2.y), acc[i][2]);
            acc[i][3] = ffma2_(dwB.y, pk2(f3.x, f3.y), acc[i][3]);
        }
    }

#pragma unroll
    for (int i = 0; i < 2; i++) {
        int p = ps * 2 + i;
        float a0, a1, a2, a3, a4, a5, a6, a7;
        upk2(acc[i][0], a0, a1);
        upk2(acc[i][1], a2, a3);
        upk2(acc[i][2], a4, a5);
        upk2(acc[i][3], a6, a7);
        __half2 m0 = __floats2half2_rn(a0, a1);
        __half2 m1 = __floats2half2_rn(a2, a3);
        __half2 m2 = __floats2half2_rn(a4, a5);
        __half2 m3 = __floats2half2_rn(a6, a7);
        uint4 mv;
        memcpy(&mv.x, &m0, 4);
        memcpy(&mv.y, &m1, 4);
        memcpy(&mv.z, &m2, 4);
        memcpy(&mv.w, &m3, 4);
        *(uint4*)(g_mid + (size_t)(pgbase + p) * 256 + c) = mv;
    }
}

// ---------------- kernel 5: fp16 2-pass GEMM (one batch chunk) ----------------
#define ROWB   80
#define W_SELB 10240
#define W_STGB 20480
#define M_BASE 40960
#define M_STGB 10240
__global__ __launch_bounds__(256, 2) void k_gemm_mma(float* __restrict__ out, int pb0) {
    extern __shared__ __align__(1024) char dyn[];
    const int tid  = threadIdx.x;
    const int warp = tid >> 5, lane = tid & 31;
    const int wo   = warp >> 2;      // 0..1  (o dim)
    const int wp   = warp & 3;       // 0..3  (px dim)
    const int pb   = pb0 + blockIdx.x, ob = blockIdx.y;

    const uint32_t uS = smem_u32(dyn);

    float acc[4][4][4];
#pragma unroll
    for (int mt = 0; mt < 4; mt++)
#pragma unroll
        for (int nt = 0; nt < 4; nt++)
#pragma unroll
            for (int j = 0; j < 4; j++) acc[mt][nt][j] = 0.f;

    const int g  = lane >> 3, rr = lane & 7;
    const int lmo = ((g & 1) * 8 + rr) * ROWB + (g >> 1) * 16;

    auto ldchunk = [&](int ch, int st) {
#pragma unroll
        for (int a = 0; a < 2; a++) {
            const __half* gp = (a == 0) ? g_whi : g_wlo;
            char* dbase = dyn + st * W_STGB + a * W_SELB;
#pragma unroll
            for (int i = 0; i < 2; i++) {
                int idx = tid + i * 256;
                int r = idx >> 2, kc8 = (idx & 3) * 8;
                cp16(dbase + r * ROWB + kc8 * 2,
                     gp + (size_t)(ob * 128 + r) * 256 + ch * 32 + kc8);
            }
        }
        {
            char* dbase = dyn + M_BASE + st * M_STGB;
#pragma unroll
            for (int i = 0; i < 2; i++) {
                int idx = tid + i * 256;
                int r = idx >> 2, kc8 = (idx & 3) * 8;
                cp16(dbase + r * ROWB + kc8 * 2,
                     g_mid + (size_t)(pb * 128 + r) * 256 + ch * 32 + kc8);
            }
        }
    };

    ldchunk(0, 0);
    cp_commit();

#pragma unroll 1
    for (int ch = 0; ch < 8; ch++) {
        int st = ch & 1;
        if (ch < 7) {
            ldchunk(ch + 1, st ^ 1);
            cp_commit();
            cp_wait<1>();
        } else {
            cp_wait<0>();
        }
        __syncthreads();

        uint32_t wbase = uS + st * W_STGB + (wo * 64) * ROWB + lmo;
        uint32_t bbase = uS + M_BASE + st * M_STGB + (wp * 32) * ROWB + lmo;

#pragma unroll
        for (int ks = 0; ks < 2; ks++) {
            int kb = ks * 32;
            uint32_t bm_[8];
            ldsm4(bm_[0], bm_[1], bm_[2], bm_[3], bbase + kb);
            ldsm4(bm_[4], bm_[5], bm_[6], bm_[7], bbase + 16 * ROWB + kb);
#pragma unroll
            for (int mt = 0; mt < 4; mt++) {
                uint32_t ah[4], al[4];
                uint32_t abase = wbase + mt * 16 * ROWB + kb;
                ldsm4(ah[0], ah[1], ah[2], ah[3], abase);
                ldsm4(al[0], al[1], al[2], al[3], abase + W_SELB);
#pragma unroll
                for (int nt = 0; nt < 4; nt++) {
                    uint32_t b0 = bm_[(nt & 1) + (nt >> 1) * 4];
                    uint32_t b1 = bm_[(nt & 1) + (nt >> 1) * 4 + 2];
                    mma_f16(acc[mt][nt], ah, b0, b1);   // hi pass
                    mma_f16(acc[mt][nt], al, b0, b1);   // lo pass
                }
            }
        }
        __syncthreads();
    }

    int pxg = pb * 128;
    int bidx = pxg >> 12;
    int hw0  = pxg & 4095;
    float* obase = out + (size_t)bidx * 1048576;
    int o_w  = ob * 128 + wo * 64;
    int px_w = hw0 + wp * 32;
#pragma unroll
    for (int mt = 0; mt < 4; mt++) {
        int r0 = o_w + mt * 16 + (lane >> 2);
        float bias0 = __ldg(g_bias + r0);
        float bias1 = __ldg(g_bias + r0 + 8);
        float* row0 = obase + (size_t)r0 * 4096;
        float* row1 = row0 + 8 * 4096;
#pragma unroll
        for (int nt = 0; nt < 4; nt++) {
            int px = px_w + nt * 8 + (lane & 3) * 2;
            float2 v0 = make_float2(fmaxf(acc[mt][nt][0] + bias0, 0.f),
                                    fmaxf(acc[mt][nt][1] + bias0, 0.f));
            float2 v1 = make_float2(fmaxf(acc[mt][nt][2] + bias1, 0.f),
                                    fmaxf(acc[mt][nt][3] + bias1, 0.f));
            *(float2*)(row0 + px) = v0;
            *(float2*)(row1 + px) = v1;
        }
    }
}

// ---------------- launch ----------------
extern "C" void kernel_launch(void* const* d_in, const int* in_sizes, int n_in,
                              void* d_out, int out_size) {
    const float* x    = (const float*)d_in[0];
    const float* gf   = (const float*)d_in[1];
    const float* offw = (const float*)d_in[2];
    const float* og   = (const float*)d_in[3];
    const float* obt  = (const float*)d_in[4];
    const float* om   = (const float*)d_in[5];
    const float* ov   = (const float*)d_in[6];
    const float* dww  = (const float*)d_in[7];
    const float* pww  = (const float*)d_in[8];
    const float* bg   = (const float*)d_in[9];
    const float* bb   = (const float*)d_in[10];
    const float* bm   = (const float*)d_in[11];
    const float* bv   = (const float*)d_in[12];
    float* out = (float*)d_out;

    static bool init = false;
    static cudaStream_t s1;
    static cudaEvent_t e0, e2, evb[4];
    if (!init) {
        cudaFuncSetAttribute(k_gemm_mma, cudaFuncAttributeMaxDynamicSharedMemorySize, 61440);
        cudaStreamCreateWithFlags(&s1, cudaStreamNonBlocking);
        cudaEventCreateWithFlags(&e0, cudaEventDisableTiming);
        cudaEventCreateWithFlags(&e2, cudaEventDisableTiming);
        for (int i = 0; i < 4; i++) cudaEventCreateWithFlags(&evb[i], cudaEventDisableTiming);
        init = true;
    }

    // fork: transpose on side stream; prep+offset on main
    cudaEventRecord(e0, 0);
    cudaStreamWaitEvent(s1, e0, 0);
    k_transpose<<<dim3(128, 8, 4), dim3(32, 8), 0, s1>>>(x);

    k_prep<<<256, 256>>>(pww, bg, bb, bm, bv, dww);
    k_offset<<<256, 256>>>(gf, offw, og, obt, om, ov);
    cudaEventRecord(e2, 0);
    cudaStreamWaitEvent(s1, e2, 0);   // s1 now has transpose done + waits offset/prep

    // pipeline: sample(b) on s1, gemm(b) on main
    for (int b = 0; b < 4; b++) {
        k_sample<<<256, 256, 0, s1>>>(b);
        cudaEventRecord(evb[b], s1);
    }
    for (int b = 0; b < 4; b++) {
        cudaStreamWaitEvent(0, evb[b], 0);
        k_gemm_mma<<<dim3(32, 2), 256, 61440>>>(out, b * 32);
    }
}

// round 12
// speedup vs baseline: 1.1537x; 1.1537x over previous
#include <cuda_runtime.h>
#include <cuda_bf16.h>
#include <cuda_fp16.h>
#include <cstdint>
#include <cstring>

#define EPS 1e-5f
typedef unsigned long long u64;

// ---------------- f32x2 packed helpers ----------------
__device__ __forceinline__ u64 pk2(float lo, float hi) {
    u64 r;
    asm("mov.b64 %0, {%1, %2};" : "=l"(r) : "f"(lo), "f"(hi));
    return r;
}
__device__ __forceinline__ void upk2(u64 v, float& lo, float& hi) {
    asm("mov.b64 {%0, %1}, %2;" : "=f"(lo), "=f"(hi) : "l"(v));
}
__device__ __forceinline__ u64 ffma2_(u64 a, u64 b, u64 c) {
    u64 d;
    asm("fma.rn.f32x2 %0, %1, %2, %3;" : "=l"(d) : "l"(a), "l"(b), "l"(c));
    return d;
}
__device__ __forceinline__ __half2 u2h(uint32_t u) {
    __half2 h;
    memcpy(&h, &u, 4);
    return h;
}

// ---------------- cp.async helpers ----------------
__device__ __forceinline__ void cp16(void* smem_dst, const void* gsrc) {
    unsigned s = (unsigned)__cvta_generic_to_shared(smem_dst);
    asm volatile("cp.async.cg.shared.global [%0], [%1], 16;" :: "r"(s), "l"(gsrc));
}
__device__ __forceinline__ void cp_commit() {
    asm volatile("cp.async.commit_group;");
}
template <int N>
__device__ __forceinline__ void cp_wait() {
    asm volatile("cp.async.wait_group %0;" :: "n"(N));
}

// ---------------- mma helpers ----------------
__device__ __forceinline__ uint32_t smem_u32(const void* p) {
    uint32_t a;
    asm("{ .reg .u64 t; cvta.to.shared.u64 t, %1; cvt.u32.u64 %0, t; }" : "=r"(a) : "l"(p));
    return a;
}
__device__ __forceinline__ void ldsm4(uint32_t& r0, uint32_t& r1, uint32_t& r2, uint32_t& r3,
                                      uint32_t addr) {
    asm volatile("ldmatrix.sync.aligned.m8n8.x4.shared.b16 {%0,%1,%2,%3}, [%4];"
                 : "=r"(r0), "=r"(r1), "=r"(r2), "=r"(r3) : "r"(addr));
}
__device__ __forceinline__ void mma_f16(float* d, const uint32_t* a, uint32_t b0, uint32_t b1) {
    asm volatile(
        "mma.sync.aligned.m16n8k16.row.col.f32.f16.f16.f32 "
        "{%0,%1,%2,%3}, {%4,%5,%6,%7}, {%8,%9}, {%0,%1,%2,%3};"
        : "+f"(d[0]), "+f"(d[1]), "+f"(d[2]), "+f"(d[3])
        : "r"(a[0]), "r"(a[1]), "r"(a[2]), "r"(a[3]), "r"(b0), "r"(b1));
}

// ---------------- scratch ----------------
__device__ __half g_x_h[4 * 64 * 64 * 256];      // [b][h][w][c] fp16
__device__ int4   g_off4[4 * 9 * 64 * 64];       // corner elem offsets (half units)
__device__ uint4  g_cwh[4 * 9 * 64 * 64];        // 4 duplicated half2 corner weights
__device__ float  g_bias[256];
__device__ __align__(16) float2 g_dwp[9][128];   // [tap][ch-pair] depthwise weights
__device__ __half g_whi[256 * 256];              // [o][c] fp16 hi
__device__ __half g_wlo[256 * 256];              // [o][c] fp16 lo (residual)
__device__ __half g_mid[16384 * 256];            // [px][c] fp16 mid

// ---------------- kernel 1: NCHW fp32 -> NHWC fp16 ----------------
__global__ void k_transpose(const float* __restrict__ x) {
    __shared__ float tile[32][33];
    int b  = blockIdx.z;
    int s0 = blockIdx.x * 32;
    int c0 = blockIdx.y * 32;
    int tx = threadIdx.x, ty = threadIdx.y;  // (32, 8)
    const float* xb = x + (size_t)b * 256 * 4096;
    __half* ob = g_x_h + (size_t)b * 4096 * 256;
#pragma unroll
    for (int i = 0; i < 32; i += 8)
        tile[ty + i][tx] = xb[(c0 + ty + i) * 4096 + s0 + tx];
    __syncthreads();
    int tid = ty * 32 + tx;
#pragma unroll
    for (int j = 0; j < 2; j++) {
        int it = tid + j * 256;
        int r  = it >> 4, pc = it & 15;
        __half2 v = __floats2half2_rn(tile[pc * 2][r], tile[pc * 2 + 1][r]);
        *(__half2*)(ob + (size_t)(s0 + r) * 256 + c0 + pc * 2) = v;
    }
}

// ---------------- kernel 2: weight prep ----------------
__global__ void k_prep(const float* __restrict__ pw, const float* __restrict__ bg,
                       const float* __restrict__ bb, const float* __restrict__ bm,
                       const float* __restrict__ bv, const float* __restrict__ dw) {
    int idx = blockIdx.x * 256 + threadIdx.x;   // 65536 total
    int c = idx & 255;
    int o = idx >> 8;
    float s = bg[o] * rsqrtf(bv[o] + EPS);
    float w = __ldg(pw + o * 256 + c) * s;
    __half hi = __float2half_rn(w);
    __half lo = __float2half_rn(w - __half2float(hi));
    g_whi[o * 256 + c] = hi;
    g_wlo[o * 256 + c] = lo;
    if (idx < 256) {
        float s2 = bg[idx] * rsqrtf(bv[idx] + EPS);
        g_bias[idx] = bb[idx] - bm[idx] * s2;
    }
    if (idx < 9 * 128) {
        int k  = idx / 128;
        int cp = idx & 127;
        g_dwp[k][cp] = make_float2(__ldg(dw + (2 * cp) * 9 + k),
                                   __ldg(dw + (2 * cp + 1) * 9 + k));
    }
}

// ---------------- kernel 3: offset conv + sampling params (4-way group split) ----------------
__global__ __launch_bounds__(256) void k_offset(const float* __restrict__ gf,
                         const float* __restrict__ offw,
                         const float* __restrict__ og, const float* __restrict__ obt,
                         const float* __restrict__ om, const float* __restrict__ ov) {
    __shared__ __align__(16) char sbuf[46080];
    float2 (*s_w2)[64][10] = (float2(*)[64][10])sbuf;
    float2 (*s_red)[64][9] = (float2(*)[64][9])sbuf;   // overlay after weights done

    int bh = blockIdx.x;
    int b = bh >> 6, h = bh & 63;
    int tid = threadIdx.x;
    int w  = tid & 63;
    int gs = tid >> 6;    // 0..3

    for (int i = tid; i < 9 * 64 * 9; i += 256) {
        int t = i % 9;
        int g = (i / 9) & 63;
        int k = i / 576;
        float wdy = offw[(2 * k) * 576 + g * 9 + t];
        float wdx = offw[(2 * k + 1) * 576 + g * 9 + t];
        s_w2[k][g][t] = make_float2(wdy, wdx);
    }
    __syncthreads();

    u64 acc[9];
#pragma unroll
    for (int k = 0; k < 9; k++) acc[k] = 0ull;

    const float* gfb = gf + (size_t)b * 64 * 64 * 64;
    int g0 = gs * 16;
    for (int gi = 0; gi < 16; gi++) {
        int g = g0 + gi;
        float a[9];
#pragma unroll
        for (int r = 0; r < 3; r++) {
            int hh = h + r - 1;
            bool hv = (unsigned)hh < 64u;
#pragma unroll
            for (int q = 0; q < 3; q++) {
                int ww = w + q - 1;
                bool wv2 = (unsigned)ww < 64u;
                a[r * 3 + q] = (hv && wv2) ? __ldg(gfb + (g * 64 + hh) * 64 + ww) : 0.f;
            }
        }
        u64 a2[9];
#pragma unroll
        for (int t = 0; t < 9; t++) a2[t] = pk2(a[t], a[t]);
#pragma unroll
        for (int k = 0; k < 9; k++) {
            const u64* wr = (const u64*)&s_w2[k][g][0];
            ulonglong2 w01 = *(const ulonglong2*)(wr + 0);
            ulonglong2 w23 = *(const ulonglong2*)(wr + 2);
            ulonglong2 w45 = *(const ulonglong2*)(wr + 4);
            ulonglong2 w67 = *(const ulonglong2*)(wr + 6);
            u64 w8 = wr[8];
            acc[k] = ffma2_(w01.x, a2[0], acc[k]);
            acc[k] = ffma2_(w01.y, a2[1], acc[k]);
            acc[k] = ffma2_(w23.x, a2[2], acc[k]);
            acc[k] = ffma2_(w23.y, a2[3], acc[k]);
            acc[k] = ffma2_(w45.x, a2[4], acc[k]);
            acc[k] = ffma2_(w45.y, a2[5], acc[k]);
            acc[k] = ffma2_(w67.x, a2[6], acc[k]);
            acc[k] = ffma2_(w67.y, a2[7], acc[k]);
            acc[k] = ffma2_(w8,    a2[8], acc[k]);
        }
    }

    __syncthreads();
#pragma unroll
    for (int k = 0; k < 9; k++) {
        float lo, hi;
        upk2(acc[k], lo, hi);
        s_red[gs][w][k] = make_float2(lo, hi);
    }
    __syncthreads();
    if (gs != 0) return;

#pragma unroll
    for (int k = 0; k < 9; k++) {
        float2 p0 = s_red[0][w][k];
        float2 p1 = s_red[1][w][k];
        float2 p2 = s_red[2][w][k];
        float2 p3 = s_red[3][w][k];
        float dyr = (p0.x + p1.x) + (p2.x + p3.x);
        float dxr = (p0.y + p1.y) + (p2.y + p3.y);

        int j0 = 2 * k, j1 = 2 * k + 1;
        float s0 = og[j0] * rsqrtf(ov[j0] + EPS);
        float s1 = og[j1] * rsqrtf(ov[j1] + EPS);
        float dy = fmaxf((dyr - om[j0]) * s0 + obt[j0], 0.f);
        float dx = fmaxf((dxr - om[j1]) * s1 + obt[j1], 0.f);
        float ky = (float)((k / 3) - 1) * 2.0f;   // DIL = 2
        float kx = (float)((k % 3) - 1) * 2.0f;
        float gy = (float)h + ky + dy;
        float gx = (float)w + kx + dx;
        float y0f = floorf(gy), x0f = floorf(gx);
        float wy = gy - y0f, wx = gx - x0f;
        float omwy = 1.f - wy, omwx = 1.f - wx;
        int y0 = (int)y0f, x0 = (int)x0f;
        bool yv0 = (unsigned)y0 < 64u;
        bool yv1 = (unsigned)(y0 + 1) < 64u;
        bool xv0 = (unsigned)x0 < 64u;
        bool xv1 = (unsigned)(x0 + 1) < 64u;
        int y0c = min(max(y0, 0), 63);
        int y1c = min(max(y0 + 1, 0), 63);
        int x0c = min(max(x0, 0), 63);
        int x1c = min(max(x0 + 1, 0), 63);
        int idx = ((b * 9 + k) * 64 + h) * 64 + w;
        g_off4[idx] = make_int4((y0c * 64 + x0c) * 256, (y0c * 64 + x1c) * 256,
                                (y1c * 64 + x0c) * 256, (y1c * 64 + x1c) * 256);
        float c00 = omwy * omwx * (float)(yv0 && xv0);
        float c01 = omwy * wx   * (float)(yv0 && xv1);
        float c10 = wy * omwx   * (float)(yv1 && xv0);
        float c11 = wy * wx     * (float)(yv1 && xv1);
        __half2 h00 = __float2half2_rn(c00);
        __half2 h01 = __float2half2_rn(c01);
        __half2 h10 = __float2half2_rn(c10);
        __half2 h11 = __float2half2_rn(c11);
        uint4 pack;
        memcpy(&pack.x, &h00, 4);
        memcpy(&pack.y, &h01, 4);
        memcpy(&pack.z, &h10, 4);
        memcpy(&pack.w, &h11, 4);
        g_cwh[idx] = pack;
    }
}

// ---------------- kernel 4: fp16 sample + depthwise (half: 2 batches, grid 512) ----------------
__global__ __launch_bounds__(256, 3) void k_sample(int t0) {
    __shared__ __align__(16) int4 s_off[9][16];
    __shared__ __align__(16) uint4 s_cwh[9][16];

    int t  = t0 + blockIdx.x;     // global tile 0..1023
    int w0 = (t & 3) << 4;
    int h  = (t >> 2) & 63;
    int b  = t >> 8;
    int tid = threadIdx.x;

    if (tid < 144) {
        int k = tid / 16, p = tid & 15;
        int idx = ((b * 9 + k) * 64 + h) * 64 + w0 + p;
        s_off[k][p] = g_off4[idx];
        s_cwh[k][p] = g_cwh[idx];
    }

    int cg = tid & 31;        // lane: 8 channels, c = cg*8
    int ps = tid >> 5;        // warp id: pixels ps*2, ps*2+1
    int c  = cg << 3;
    __syncthreads();

    const __half* xh = g_x_h + (size_t)b * 4096 * 256 + c;
    int pgbase = b * 4096 + h * 64 + w0;

    u64 acc[2][4];
#pragma unroll
    for (int i = 0; i < 2; i++)
#pragma unroll
        for (int j = 0; j < 4; j++) acc[i][j] = 0ull;

#pragma unroll
    for (int k = 0; k < 9; k++) {
        ulonglong2 dwA = *(const ulonglong2*)&g_dwp[k][cg * 4];
        ulonglong2 dwB = *(const ulonglong2*)&g_dwp[k][cg * 4 + 2];
#pragma unroll
        for (int i = 0; i < 2; i++) {
            int p = ps * 2 + i;
            int4 o4 = s_off[k][p];
            uint4 r00 = __ldg((const uint4*)(xh + o4.x));
            uint4 r01 = __ldg((const uint4*)(xh + o4.y));
            uint4 r10 = __ldg((const uint4*)(xh + o4.z));
            uint4 r11 = __ldg((const uint4*)(xh + o4.w));
            uint4 cw = s_cwh[k][p];
            __half2 w00 = u2h(cw.x), w01 = u2h(cw.y), w10 = u2h(cw.z), w11 = u2h(cw.w);
            __half2 v0 = __hmul2(w00, u2h(r00.x));
            __half2 v1 = __hmul2(w00, u2h(r00.y));
            __half2 v2 = __hmul2(w00, u2h(r00.z));
            __half2 v3 = __hmul2(w00, u2h(r00.w));
            v0 = __hfma2(w01, u2h(r01.x), v0);
            v1 = __hfma2(w01, u2h(r01.y), v1);
            v2 = __hfma2(w01, u2h(r01.z), v2);
            v3 = __hfma2(w01, u2h(r01.w), v3);
            v0 = __hfma2(w10, u2h(r10.x), v0);
            v1 = __hfma2(w10, u2h(r10.y), v1);
            v2 = __hfma2(w10, u2h(r10.z), v2);
            v3 = __hfma2(w10, u2h(r10.w), v3);
            v0 = __hfma2(w11, u2h(r11.x), v0);
            v1 = __hfma2(w11, u2h(r11.y), v1);
            v2 = __hfma2(w11, u2h(r11.z), v2);
            v3 = __hfma2(w11, u2h(r11.w), v3);
            float2 f0 = __half22float2(v0);
            float2 f1 = __half22float2(v1);
            float2 f2 = __half22float2(v2);
            float2 f3 = __half22float2(v3);
            acc[i][0] = ffma2_(dwA.x, pk2(f0.x, f0.y), acc[i][0]);
            acc[i][1] = ffma2_(dwA.y, pk2(f1.x, f1.y), acc[i][1]);
            acc[i][2] = ffma2_(dwB.x, pk2(f2.x, f2.y), acc[i][2]);
            acc[i][3] = ffma2_(dwB.y, pk2(f3.x, f3.y), acc[i][3]);
        }
    }

#pragma unroll
    for (int i = 0; i < 2; i++) {
        int p = ps * 2 + i;
        float a0, a1, a2, a3, a4, a5, a6, a7;
        upk2(acc[i][0], a0, a1);
        upk2(acc[i][1], a2, a3);
        upk2(acc[i][2], a4, a5);
        upk2(acc[i][3], a6, a7);
        __half2 m0 = __floats2half2_rn(a0, a1);
        __half2 m1 = __floats2half2_rn(a2, a3);
        __half2 m2 = __floats2half2_rn(a4, a5);
        __half2 m3 = __floats2half2_rn(a6, a7);
        uint4 mv;
        memcpy(&mv.x, &m0, 4);
        memcpy(&mv.y, &m1, 4);
        memcpy(&mv.z, &m2, 4);
        memcpy(&mv.w, &m3, 4);
        *(uint4*)(g_mid + (size_t)(pgbase + p) * 256 + c) = mv;
    }
}

// ---------------- kernel 5: fp16 2-pass GEMM (half: grid 64 x 2) ----------------
#define ROWB   80
#define W_SELB 10240
#define W_STGB 20480
#define M_BASE 40960
#define M_STGB 10240
__global__ __launch_bounds__(256, 2) void k_gemm_mma(float* __restrict__ out, int pb0) {
    extern __shared__ __align__(1024) char dyn[];
    const int tid  = threadIdx.x;
    const int warp = tid >> 5, lane = tid & 31;
    const int wo   = warp >> 2;      // 0..1  (o dim)
    const int wp   = warp & 3;       // 0..3  (px dim)
    const int pb   = pb0 + blockIdx.x, ob = blockIdx.y;

    const uint32_t uS = smem_u32(dyn);

    float acc[4][4][4];
#pragma unroll
    for (int mt = 0; mt < 4; mt++)
#pragma unroll
        for (int nt = 0; nt < 4; nt++)
#pragma unroll
            for (int j = 0; j < 4; j++) acc[mt][nt][j] = 0.f;

    const int g  = lane >> 3, rr = lane & 7;
    const int lmo = ((g & 1) * 8 + rr) * ROWB + (g >> 1) * 16;

    auto ldchunk = [&](int ch, int st) {
#pragma unroll
        for (int a = 0; a < 2; a++) {
            const __half* gp = (a == 0) ? g_whi : g_wlo;
            char* dbase = dyn + st * W_STGB + a * W_SELB;
#pragma unroll
            for (int i = 0; i < 2; i++) {
                int idx = tid + i * 256;
                int r = idx >> 2, kc8 = (idx & 3) * 8;
                cp16(dbase + r * ROWB + kc8 * 2,
                     gp + (size_t)(ob * 128 + r) * 256 + ch * 32 + kc8);
            }
        }
        {
            char* dbase = dyn + M_BASE + st * M_STGB;
#pragma unroll
            for (int i = 0; i < 2; i++) {
                int idx = tid + i * 256;
                int r = idx >> 2, kc8 = (idx & 3) * 8;
                cp16(dbase + r * ROWB + kc8 * 2,
                     g_mid + (size_t)(pb * 128 + r) * 256 + ch * 32 + kc8);
            }
        }
    };

    ldchunk(0, 0);
    cp_commit();

#pragma unroll 1
    for (int ch = 0; ch < 8; ch++) {
        int st = ch & 1;
        if (ch < 7) {
            ldchunk(ch + 1, st ^ 1);
            cp_commit();
            cp_wait<1>();
        } else {
            cp_wait<0>();
        }
        __syncthreads();

        uint32_t wbase = uS + st * W_STGB + (wo * 64) * ROWB + lmo;
        uint32_t bbase = uS + M_BASE + st * M_STGB + (wp * 32) * ROWB + lmo;

#pragma unroll
        for (int ks = 0; ks < 2; ks++) {
            int kb = ks * 32;
            uint32_t bm_[8];
            ldsm4(bm_[0], bm_[1], bm_[2], bm_[3], bbase + kb);
            ldsm4(bm_[4], bm_[5], bm_[6], bm_[7], bbase + 16 * ROWB + kb);
#pragma unroll
            for (int mt = 0; mt < 4; mt++) {
                uint32_t ah[4], al[4];
                uint32_t abase = wbase + mt * 16 * ROWB + kb;
                ldsm4(ah[0], ah[1], ah[2], ah[3], abase);
                ldsm4(al[0], al[1], al[2], al[3], abase + W_SELB);
#pragma unroll
                for (int nt = 0; nt < 4; nt++) {
                    uint32_t b0 = bm_[(nt & 1) + (nt >> 1) * 4];
                    uint32_t b1 = bm_[(nt & 1) + (nt >> 1) * 4 + 2];
                    mma_f16(acc[mt][nt], ah, b0, b1);   // hi pass
                    mma_f16(acc[mt][nt], al, b0, b1);   // lo pass
                }
            }
        }
        __syncthreads();
    }

    int pxg = pb * 128;
    int bidx = pxg >> 12;
    int hw0  = pxg & 4095;
    float* obase = out + (size_t)bidx * 1048576;
    int o_w  = ob * 128 + wo * 64;
    int px_w = hw0 + wp * 32;
#pragma unroll
    for (int mt = 0; mt < 4; mt++) {
        int r0 = o_w + mt * 16 + (lane >> 2);
        float bias0 = __ldg(g_bias + r0);
        float bias1 = __ldg(g_bias + r0 + 8);
        float* row0 = obase + (size_t)r0 * 4096;
        float* row1 = row0 + 8 * 4096;
#pragma unroll
        for (int nt = 0; nt < 4; nt++) {
            int px = px_w + nt * 8 + (lane & 3) * 2;
            float2 v0 = make_float2(fmaxf(acc[mt][nt][0] + bias0, 0.f),
                                    fmaxf(acc[mt][nt][1] + bias0, 0.f));
            float2 v1 = make_float2(fmaxf(acc[mt][nt][2] + bias1, 0.f),
                                    fmaxf(acc[mt][nt][3] + bias1, 0.f));
            *(float2*)(row0 + px) = v0;
            *(float2*)(row1 + px) = v1;
        }
    }
}

// ---------------- launch ----------------
extern "C" void kernel_launch(void* const* d_in, const int* in_sizes, int n_in,
                              void* d_out, int out_size) {
    const float* x    = (const float*)d_in[0];
    const float* gf   = (const float*)d_in[1];
    const float* offw = (const float*)d_in[2];
    const float* og   = (const float*)d_in[3];
    const float* obt  = (const float*)d_in[4];
    const float* om   = (const float*)d_in[5];
    const float* ov   = (const float*)d_in[6];
    const float* dww  = (const float*)d_in[7];
    const float* pww  = (const float*)d_in[8];
    const float* bg   = (const float*)d_in[9];
    const float* bb   = (const float*)d_in[10];
    const float* bm   = (const float*)d_in[11];
    const float* bv   = (const float*)d_in[12];
    float* out = (float*)d_out;

    static bool init = false;
    static cudaStream_t s1;
    static cudaEvent_t e0, e2, ev0, ev1;
    if (!init) {
        cudaFuncSetAttribute(k_gemm_mma, cudaFuncAttributeMaxDynamicSharedMemorySize, 61440);
        cudaStreamCreateWithFlags(&s1, cudaStreamNonBlocking);
        cudaEventCreateWithFlags(&e0, cudaEventDisableTiming);
        cudaEventCreateWithFlags(&e2, cudaEventDisableTiming);
        cudaEventCreateWithFlags(&ev0, cudaEventDisableTiming);
        cudaEventCreateWithFlags(&ev1, cudaEventDisableTiming);
        init = true;
    }

    // fork: transpose on side stream; prep+offset on main
    cudaEventRecord(e0, 0);
    cudaStreamWaitEvent(s1, e0, 0);
    k_transpose<<<dim3(128, 8, 4), dim3(32, 8), 0, s1>>>(x);

    k_prep<<<256, 256>>>(pww, bg, bb, bm, bv, dww);
    k_offset<<<256, 256>>>(gf, offw, og, obt, om, ov);
    cudaEventRecord(e2, 0);
    cudaStreamWaitEvent(s1, e2, 0);

    // 2-half pipeline: sample halves on s1, gemm halves on main
    k_sample<<<512, 256, 0, s1>>>(0);
    cudaEventRecord(ev0, s1);
    k_sample<<<512, 256, 0, s1>>>(512);
    cudaEventRecord(ev1, s1);

    cudaStreamWaitEvent(0, ev0, 0);
    k_gemm_mma<<<dim3(64, 2), 256, 61440>>>(out, 0);
    cudaStreamWaitEvent(0, ev1, 0);
    k_gemm_mma<<<dim3(64, 2), 256, 61440>>>(out, 64);
}

// round 13
// speedup vs baseline: 1.3237x; 1.1474x over previous
#include <cuda_runtime.h>
#include <cuda_bf16.h>
#include <cuda_fp16.h>
#include <cstdint>
#include <cstring>

#define EPS 1e-5f
typedef unsigned long long u64;

// ---------------- f32x2 packed helpers ----------------
__device__ __forceinline__ u64 pk2(float lo, float hi) {
    u64 r;
    asm("mov.b64 %0, {%1, %2};" : "=l"(r) : "f"(lo), "f"(hi));
    return r;
}
__device__ __forceinline__ void upk2(u64 v, float& lo, float& hi) {
    asm("mov.b64 {%0, %1}, %2;" : "=f"(lo), "=f"(hi) : "l"(v));
}
__device__ __forceinline__ u64 ffma2_(u64 a, u64 b, u64 c) {
    u64 d;
    asm("fma.rn.f32x2 %0, %1, %2, %3;" : "=l"(d) : "l"(a), "l"(b), "l"(c));
    return d;
}
__device__ __forceinline__ __half2 u2h(uint32_t u) {
    __half2 h;
    memcpy(&h, &u, 4);
    return h;
}

// ---------------- cp.async helpers ----------------
__device__ __forceinline__ void cp16(void* smem_dst, const void* gsrc) {
    unsigned s = (unsigned)__cvta_generic_to_shared(smem_dst);
    asm volatile("cp.async.cg.shared.global [%0], [%1], 16;" :: "r"(s), "l"(gsrc));
}
__device__ __forceinline__ void cp_commit() {
    asm volatile("cp.async.commit_group;");
}
template <int N>
__device__ __forceinline__ void cp_wait() {
    asm volatile("cp.async.wait_group %0;" :: "n"(N));
}

// ---------------- mma helpers ----------------
__device__ __forceinline__ uint32_t smem_u32(const void* p) {
    uint32_t a;
    asm("{ .reg .u64 t; cvta.to.shared.u64 t, %1; cvt.u32.u64 %0, t; }" : "=r"(a) : "l"(p));
    return a;
}
__device__ __forceinline__ void ldsm4(uint32_t& r0, uint32_t& r1, uint32_t& r2, uint32_t& r3,
                                      uint32_t addr) {
    asm volatile("ldmatrix.sync.aligned.m8n8.x4.shared.b16 {%0,%1,%2,%3}, [%4];"
                 : "=r"(r0), "=r"(r1), "=r"(r2), "=r"(r3) : "r"(addr));
}
__device__ __forceinline__ void mma_f16(float* d, const uint32_t* a, uint32_t b0, uint32_t b1) {
    asm volatile(
        "mma.sync.aligned.m16n8k16.row.col.f32.f16.f16.f32 "
        "{%0,%1,%2,%3}, {%4,%5,%6,%7}, {%8,%9}, {%0,%1,%2,%3};"
        : "+f"(d[0]), "+f"(d[1]), "+f"(d[2]), "+f"(d[3])
        : "r"(a[0]), "r"(a[1]), "r"(a[2]), "r"(a[3]), "r"(b0), "r"(b1));
}

// ---------------- scratch ----------------
__device__ __half g_x_h[4 * 64 * 64 * 256];      // [b][h][w][c] fp16
__device__ int4   g_off4[4 * 9 * 64 * 64];       // corner elem offsets (half units)
__device__ uint4  g_cwh[4 * 9 * 64 * 64];        // 4 duplicated half2 corner weights
__device__ float  g_bias[256];
__device__ __align__(16) float2 g_dwp[9][128];   // [tap][ch-pair] depthwise weights
__device__ __half g_wh[256 * 256];               // [o][c] fp16 weights (BN folded)
__device__ __half g_mid[16384 * 256];            // [px][c] fp16 mid

// ---------------- kernel 1: NCHW fp32 -> NHWC fp16 ----------------
__global__ void k_transpose(const float* __restrict__ x) {
    __shared__ float tile[32][33];
    int b  = blockIdx.z;
    int s0 = blockIdx.x * 32;
    int c0 = blockIdx.y * 32;
    int tx = threadIdx.x, ty = threadIdx.y;  // (32, 8)
    const float* xb = x + (size_t)b * 256 * 4096;
    __half* ob = g_x_h + (size_t)b * 4096 * 256;
#pragma unroll
    for (int i = 0; i < 32; i += 8)
        tile[ty + i][tx] = xb[(c0 + ty + i) * 4096 + s0 + tx];
    __syncthreads();
    int tid = ty * 32 + tx;
#pragma unroll
    for (int j = 0; j < 2; j++) {
        int it = tid + j * 256;
        int r  = it >> 4, pc = it & 15;
        __half2 v = __floats2half2_rn(tile[pc * 2][r], tile[pc * 2 + 1][r]);
        *(__half2*)(ob + (size_t)(s0 + r) * 256 + c0 + pc * 2) = v;
    }
}

// ---------------- kernel 2: weight prep ----------------
__global__ void k_prep(const float* __restrict__ pw, const float* __restrict__ bg,
                       const float* __restrict__ bb, const float* __restrict__ bm,
                       const float* __restrict__ bv, const float* __restrict__ dw) {
    int idx = blockIdx.x * 256 + threadIdx.x;   // 65536 total
    int c = idx & 255;
    int o = idx >> 8;
    float s = bg[o] * rsqrtf(bv[o] + EPS);
    float w = __ldg(pw + o * 256 + c) * s;
    g_wh[o * 256 + c] = __float2half_rn(w);
    if (idx < 256) {
        float s2 = bg[idx] * rsqrtf(bv[idx] + EPS);
        g_bias[idx] = bb[idx] - bm[idx] * s2;
    }
    if (idx < 9 * 128) {
        int k  = idx / 128;
        int cp = idx & 127;
        g_dwp[k][cp] = make_float2(__ldg(dw + (2 * cp) * 9 + k),
                                   __ldg(dw + (2 * cp + 1) * 9 + k));
    }
}

// ---------------- kernel 3: offset conv + sampling params (4-way group split) ----------------
__global__ __launch_bounds__(256) void k_offset(const float* __restrict__ gf,
                         const float* __restrict__ offw,
                         const float* __restrict__ og, const float* __restrict__ obt,
                         const float* __restrict__ om, const float* __restrict__ ov) {
    __shared__ __align__(16) char sbuf[46080];
    float2 (*s_w2)[64][10] = (float2(*)[64][10])sbuf;
    float2 (*s_red)[64][9] = (float2(*)[64][9])sbuf;   // overlay after weights done

    int bh = blockIdx.x;
    int b = bh >> 6, h = bh & 63;
    int tid = threadIdx.x;
    int w  = tid & 63;
    int gs = tid >> 6;    // 0..3

    for (int i = tid; i < 9 * 64 * 9; i += 256) {
        int t = i % 9;
        int g = (i / 9) & 63;
        int k = i / 576;
        float wdy = offw[(2 * k) * 576 + g * 9 + t];
        float wdx = offw[(2 * k + 1) * 576 + g * 9 + t];
        s_w2[k][g][t] = make_float2(wdy, wdx);
    }
    __syncthreads();

    u64 acc[9];
#pragma unroll
    for (int k = 0; k < 9; k++) acc[k] = 0ull;

    const float* gfb = gf + (size_t)b * 64 * 64 * 64;
    int g0 = gs * 16;
    for (int gi = 0; gi < 16; gi++) {
        int g = g0 + gi;
        float a[9];
#pragma unroll
        for (int r = 0; r < 3; r++) {
            int hh = h + r - 1;
            bool hv = (unsigned)hh < 64u;
#pragma unroll
            for (int q = 0; q < 3; q++) {
                int ww = w + q - 1;
                bool wv2 = (unsigned)ww < 64u;
                a[r * 3 + q] = (hv && wv2) ? __ldg(gfb + (g * 64 + hh) * 64 + ww) : 0.f;
            }
        }
        u64 a2[9];
#pragma unroll
        for (int t = 0; t < 9; t++) a2[t] = pk2(a[t], a[t]);
#pragma unroll
        for (int k = 0; k < 9; k++) {
            const u64* wr = (const u64*)&s_w2[k][g][0];
            ulonglong2 w01 = *(const ulonglong2*)(wr + 0);
            ulonglong2 w23 = *(const ulonglong2*)(wr + 2);
            ulonglong2 w45 = *(const ulonglong2*)(wr + 4);
            ulonglong2 w67 = *(const ulonglong2*)(wr + 6);
            u64 w8 = wr[8];
            acc[k] = ffma2_(w01.x, a2[0], acc[k]);
            acc[k] = ffma2_(w01.y, a2[1], acc[k]);
            acc[k] = ffma2_(w23.x, a2[2], acc[k]);
            acc[k] = ffma2_(w23.y, a2[3], acc[k]);
            acc[k] = ffma2_(w45.x, a2[4], acc[k]);
            acc[k] = ffma2_(w45.y, a2[5], acc[k]);
            acc[k] = ffma2_(w67.x, a2[6], acc[k]);
            acc[k] = ffma2_(w67.y, a2[7], acc[k]);
            acc[k] = ffma2_(w8,    a2[8], acc[k]);
        }
    }

    __syncthreads();
#pragma unroll
    for (int k = 0; k < 9; k++) {
        float lo, hi;
        upk2(acc[k], lo, hi);
        s_red[gs][w][k] = make_float2(lo, hi);
    }
    __syncthreads();
    if (gs != 0) return;

#pragma unroll
    for (int k = 0; k < 9; k++) {
        float2 p0 = s_red[0][w][k];
        float2 p1 = s_red[1][w][k];
        float2 p2 = s_red[2][w][k];
        float2 p3 = s_red[3][w][k];
        float dyr = (p0.x + p1.x) + (p2.x + p3.x);
        float dxr = (p0.y + p1.y) + (p2.y + p3.y);

        int j0 = 2 * k, j1 = 2 * k + 1;
        float s0 = og[j0] * rsqrtf(ov[j0] + EPS);
        float s1 = og[j1] * rsqrtf(ov[j1] + EPS);
        float dy = fmaxf((dyr - om[j0]) * s0 + obt[j0], 0.f);
        float dx = fmaxf((dxr - om[j1]) * s1 + obt[j1], 0.f);
        float ky = (float)((k / 3) - 1) * 2.0f;   // DIL = 2
        float kx = (float)((k % 3) - 1) * 2.0f;
        float gy = (float)h + ky + dy;
        float gx = (float)w + kx + dx;
        float y0f = floorf(gy), x0f = floorf(gx);
        float wy = gy - y0f, wx = gx - x0f;
        float omwy = 1.f - wy, omwx = 1.f - wx;
        int y0 = (int)y0f, x0 = (int)x0f;
        bool yv0 = (unsigned)y0 < 64u;
        bool yv1 = (unsigned)(y0 + 1) < 64u;
        bool xv0 = (unsigned)x0 < 64u;
        bool xv1 = (unsigned)(x0 + 1) < 64u;
        int y0c = min(max(y0, 0), 63);
        int y1c = min(max(y0 + 1, 0), 63);
        int x0c = min(max(x0, 0), 63);
        int x1c = min(max(x0 + 1, 0), 63);
        int idx = ((b * 9 + k) * 64 + h) * 64 + w;
        g_off4[idx] = make_int4((y0c * 64 + x0c) * 256, (y0c * 64 + x1c) * 256,
                                (y1c * 64 + x0c) * 256, (y1c * 64 + x1c) * 256);
        float c00 = omwy * omwx * (float)(yv0 && xv0);
        float c01 = omwy * wx   * (float)(yv0 && xv1);
        float c10 = wy * omwx   * (float)(yv1 && xv0);
        float c11 = wy * wx     * (float)(yv1 && xv1);
        __half2 h00 = __float2half2_rn(c00);
        __half2 h01 = __float2half2_rn(c01);
        __half2 h10 = __float2half2_rn(c10);
        __half2 h11 = __float2half2_rn(c11);
        uint4 pack;
        memcpy(&pack.x, &h00, 4);
        memcpy(&pack.y, &h01, 4);
        memcpy(&pack.z, &h10, 4);
        memcpy(&pack.w, &h11, 4);
        g_cwh[idx] = pack;
    }
}

// ---------------- kernel 4: fp16 sample + depthwise (half: grid 512) ----------------
__global__ __launch_bounds__(256, 3) void k_sample(int t0) {
    __shared__ __align__(16) int4 s_off[9][16];
    __shared__ __align__(16) uint4 s_cwh[9][16];

    int t  = t0 + blockIdx.x;     // global tile 0..1023
    int w0 = (t & 3) << 4;
    int h  = (t >> 2) & 63;
    int b  = t >> 8;
    int tid = threadIdx.x;

    if (tid < 144) {
        int k = tid / 16, p = tid & 15;
        int idx = ((b * 9 + k) * 64 + h) * 64 + w0 + p;
        s_off[k][p] = g_off4[idx];
        s_cwh[k][p] = g_cwh[idx];
    }

    int cg = tid & 31;        // lane: 8 channels, c = cg*8
    int ps = tid >> 5;        // warp id: pixels ps*2, ps*2+1
    int c  = cg << 3;
    __syncthreads();

    const __half* xh = g_x_h + (size_t)b * 4096 * 256 + c;
    int pgbase = b * 4096 + h * 64 + w0;

    u64 acc[2][4];
#pragma unroll
    for (int i = 0; i < 2; i++)
#pragma unroll
        for (int j = 0; j < 4; j++) acc[i][j] = 0ull;

#pragma unroll
    for (int k = 0; k < 9; k++) {
        ulonglong2 dwA = *(const ulonglong2*)&g_dwp[k][cg * 4];
        ulonglong2 dwB = *(const ulonglong2*)&g_dwp[k][cg * 4 + 2];
#pragma unroll
        for (int i = 0; i < 2; i++) {
            int p = ps * 2 + i;
            int4 o4 = s_off[k][p];
            uint4 r00 = __ldg((const uint4*)(xh + o4.x));
            uint4 r01 = __ldg((const uint4*)(xh + o4.y));
            uint4 r10 = __ldg((const uint4*)(xh + o4.z));
            uint4 r11 = __ldg((const uint4*)(xh + o4.w));
            uint4 cw = s_cwh[k][p];
            __half2 w00 = u2h(cw.x), w01 = u2h(cw.y), w10 = u2h(cw.z), w11 = u2h(cw.w);
            __half2 v0 = __hmul2(w00, u2h(r00.x));
            __half2 v1 = __hmul2(w00, u2h(r00.y));
            __half2 v2 = __hmul2(w00, u2h(r00.z));
            __half2 v3 = __hmul2(w00, u2h(r00.w));
            v0 = __hfma2(w01, u2h(r01.x), v0);
            v1 = __hfma2(w01, u2h(r01.y), v1);
            v2 = __hfma2(w01, u2h(r01.z), v2);
            v3 = __hfma2(w01, u2h(r01.w), v3);
            v0 = __hfma2(w10, u2h(r10.x), v0);
            v1 = __hfma2(w10, u2h(r10.y), v1);
            v2 = __hfma2(w10, u2h(r10.z), v2);
            v3 = __hfma2(w10, u2h(r10.w), v3);
            v0 = __hfma2(w11, u2h(r11.x), v0);
            v1 = __hfma2(w11, u2h(r11.y), v1);
            v2 = __hfma2(w11, u2h(r11.z), v2);
            v3 = __hfma2(w11, u2h(r11.w), v3);
            float2 f0 = __half22float2(v0);
            float2 f1 = __half22float2(v1);
            float2 f2 = __half22float2(v2);
            float2 f3 = __half22float2(v3);
            acc[i][0] = ffma2_(dwA.x, pk2(f0.x, f0.y), acc[i][0]);
            acc[i][1] = ffma2_(dwA.y, pk2(f1.x, f1.y), acc[i][1]);
            acc[i][2] = ffma2_(dwB.x, pk2(f2.x, f2.y), acc[i][2]);
            acc[i][3] = ffma2_(dwB.y, pk2(f3.x, f3.y), acc[i][3]);
        }
    }

#pragma unroll
    for (int i = 0; i < 2; i++) {
        int p = ps * 2 + i;
        float a0, a1, a2, a3, a4, a5, a6, a7;
        upk2(acc[i][0], a0, a1);
        upk2(acc[i][1], a2, a3);
        upk2(acc[i][2], a4, a5);
        upk2(acc[i][3], a6, a7);
        __half2 m0 = __floats2half2_rn(a0, a1);
        __half2 m1 = __floats2half2_rn(a2, a3);
        __half2 m2 = __floats2half2_rn(a4, a5);
        __half2 m3 = __floats2half2_rn(a6, a7);
        uint4 mv;
        memcpy(&mv.x, &m0, 4);
        memcpy(&mv.y, &m1, 4);
        memcpy(&mv.z, &m2, 4);
        memcpy(&mv.w, &m3, 4);
        *(uint4*)(g_mid + (size_t)(pgbase + p) * 256 + c) = mv;
    }
}

// ---------------- kernel 5: fp16 single-pass GEMM (half: grid 64 x 2) ----------------
#define ROWB   80
#define W_STGB 10240
#define M_BASE 20480
#define M_STGB 10240
__global__ __launch_bounds__(256, 2) void k_gemm_mma(float* __restrict__ out, int pb0) {
    extern __shared__ __align__(1024) char dyn[];
    const int tid  = threadIdx.x;
    const int warp = tid >> 5, lane = tid & 31;
    const int wo   = warp >> 2;      // 0..1  (o dim)
    const int wp   = warp & 3;       // 0..3  (px dim)
    const int pb   = pb0 + blockIdx.x, ob = blockIdx.y;

    const uint32_t uS = smem_u32(dyn);

    float acc[4][4][4];
#pragma unroll
    for (int mt = 0; mt < 4; mt++)
#pragma unroll
        for (int nt = 0; nt < 4; nt++)
#pragma unroll
            for (int j = 0; j < 4; j++) acc[mt][nt][j] = 0.f;

    const int g  = lane >> 3, rr = lane & 7;
    const int lmo = ((g & 1) * 8 + rr) * ROWB + (g >> 1) * 16;

    auto ldchunk = [&](int ch, int st) {
        {
            char* dbase = dyn + st * W_STGB;
#pragma unroll
            for (int i = 0; i < 2; i++) {
                int idx = tid + i * 256;
                int r = idx >> 2, kc8 = (idx & 3) * 8;
                cp16(dbase + r * ROWB + kc8 * 2,
                     g_wh + (size_t)(ob * 128 + r) * 256 + ch * 32 + kc8);
            }
        }
        {
            char* dbase = dyn + M_BASE + st * M_STGB;
#pragma unroll
            for (int i = 0; i < 2; i++) {
                int idx = tid + i * 256;
                int r = idx >> 2, kc8 = (idx & 3) * 8;
                cp16(dbase + r * ROWB + kc8 * 2,
                     g_mid + (size_t)(pb * 128 + r) * 256 + ch * 32 + kc8);
            }
        }
    };

    ldchunk(0, 0);
    cp_commit();

#pragma unroll 1
    for (int ch = 0; ch < 8; ch++) {
        int st = ch & 1;
        if (ch < 7) {
            ldchunk(ch + 1, st ^ 1);
            cp_commit();
            cp_wait<1>();
        } else {
            cp_wait<0>();
        }
        __syncthreads();

        uint32_t wbase = uS + st * W_STGB + (wo * 64) * ROWB + lmo;
        uint32_t bbase = uS + M_BASE + st * M_STGB + (wp * 32) * ROWB + lmo;

#pragma unroll
        for (int ks = 0; ks < 2; ks++) {
            int kb = ks * 32;
            uint32_t bm_[8];
            ldsm4(bm_[0], bm_[1], bm_[2], bm_[3], bbase + kb);
            ldsm4(bm_[4], bm_[5], bm_[6], bm_[7], bbase + 16 * ROWB + kb);
#pragma unroll
            for (int mt = 0; mt < 4; mt++) {
                uint32_t ah[4];
                uint32_t abase = wbase + mt * 16 * ROWB + kb;
                ldsm4(ah[0], ah[1], ah[2], ah[3], abase);
#pragma unroll
                for (int nt = 0; nt < 4; nt++) {
                    uint32_t b0 = bm_[(nt & 1) + (nt >> 1) * 4];
                    uint32_t b1 = bm_[(nt & 1) + (nt >> 1) * 4 + 2];
                    mma_f16(acc[mt][nt], ah, b0, b1);
                }
            }
        }
        __syncthreads();
    }

    int pxg = pb * 128;
    int bidx = pxg >> 12;
    int hw0  = pxg & 4095;
    float* obase = out + (size_t)bidx * 1048576;
    int o_w  = ob * 128 + wo * 64;
    int px_w = hw0 + wp * 32;
#pragma unroll
    for (int mt = 0; mt < 4; mt++) {
        int r0 = o_w + mt * 16 + (lane >> 2);
        float bias0 = __ldg(g_bias + r0);
        float bias1 = __ldg(g_bias + r0 + 8);
        float* row0 = obase + (size_t)r0 * 4096;
        float* row1 = row0 + 8 * 4096;
#pragma unroll
        for (int nt = 0; nt < 4; nt++) {
            int px = px_w + nt * 8 + (lane & 3) * 2;
            float2 v0 = make_float2(fmaxf(acc[mt][nt][0] + bias0, 0.f),
                                    fmaxf(acc[mt][nt][1] + bias0, 0.f));
            float2 v1 = make_float2(fmaxf(acc[mt][nt][2] + bias1, 0.f),
                                    fmaxf(acc[mt][nt][3] + bias1, 0.f));
            *(float2*)(row0 + px) = v0;
            *(float2*)(row1 + px) = v1;
        }
    }
}

// ---------------- launch ----------------
extern "C" void kernel_launch(void* const* d_in, const int* in_sizes, int n_in,
                              void* d_out, int out_size) {
    const float* x    = (const float*)d_in[0];
    const float* gf   = (const float*)d_in[1];
    const float* offw = (const float*)d_in[2];
    const float* og   = (const float*)d_in[3];
    const float* obt  = (const float*)d_in[4];
    const float* om   = (const float*)d_in[5];
    const float* ov   = (const float*)d_in[6];
    const float* dww  = (const float*)d_in[7];
    const float* pww  = (const float*)d_in[8];
    const float* bg   = (const float*)d_in[9];
    const float* bb   = (const float*)d_in[10];
    const float* bm   = (const float*)d_in[11];
    const float* bv   = (const float*)d_in[12];
    float* out = (float*)d_out;

    static bool init = false;
    static cudaStream_t s1;
    static cudaEvent_t e0, e2, ev0, ev1;
    if (!init) {
        cudaFuncSetAttribute(k_gemm_mma, cudaFuncAttributeMaxDynamicSharedMemorySize, 40960);
        cudaStreamCreateWithFlags(&s1, cudaStreamNonBlocking);
        cudaEventCreateWithFlags(&e0, cudaEventDisableTiming);
        cudaEventCreateWithFlags(&e2, cudaEventDisableTiming);
        cudaEventCreateWithFlags(&ev0, cudaEventDisableTiming);
        cudaEventCreateWithFlags(&ev1, cudaEventDisableTiming);
        init = true;
    }

    // fork: transpose on side stream; prep+offset on main
    cudaEventRecord(e0, 0);
    cudaStreamWaitEvent(s1, e0, 0);
    k_transpose<<<dim3(128, 8, 4), dim3(32, 8), 0, s1>>>(x);

    k_prep<<<256, 256>>>(pww, bg, bb, bm, bv, dww);
    k_offset<<<256, 256>>>(gf, offw, og, obt, om, ov);
    cudaEventRecord(e2, 0);
    cudaStreamWaitEvent(s1, e2, 0);

    // 2-half pipeline: sample halves on s1, gemm halves on main
    k_sample<<<512, 256, 0, s1>>>(0);
    cudaEventRecord(ev0, s1);
    k_sample<<<512, 256, 0, s1>>>(512);
    cudaEventRecord(ev1, s1);

    cudaStreamWaitEvent(0, ev0, 0);
    k_gemm_mma<<<dim3(64, 2), 256, 40960>>>(out, 0);
    cudaStreamWaitEvent(0, ev1, 0);
    k_gemm_mma<<<dim3(64, 2), 256, 40960>>>(out, 64);
}

// round 14
// speedup vs baseline: 1.3631x; 1.0298x over previous
#include <cuda_runtime.h>
#include <cuda_bf16.h>
#include <cuda_fp16.h>
#include <cstdint>
#include <cstring>

#define EPS 1e-5f
typedef unsigned long long u64;

// ---------------- f32x2 packed helpers ----------------
__device__ __forceinline__ u64 pk2(float lo, float hi) {
    u64 r;
    asm("mov.b64 %0, {%1, %2};" : "=l"(r) : "f"(lo), "f"(hi));
    return r;
}
__device__ __forceinline__ void upk2(u64 v, float& lo, float& hi) {
    asm("mov.b64 {%0, %1}, %2;" : "=f"(lo), "=f"(hi) : "l"(v));
}
__device__ __forceinline__ u64 ffma2_(u64 a, u64 b, u64 c) {
    u64 d;
    asm("fma.rn.f32x2 %0, %1, %2, %3;" : "=l"(d) : "l"(a), "l"(b), "l"(c));
    return d;
}
__device__ __forceinline__ __half2 u2h(uint32_t u) {
    __half2 h;
    memcpy(&h, &u, 4);
    return h;
}

// ---------------- cp.async helpers ----------------
__device__ __forceinline__ void cp16(void* smem_dst, const void* gsrc) {
    unsigned s = (unsigned)__cvta_generic_to_shared(smem_dst);
    asm volatile("cp.async.cg.shared.global [%0], [%1], 16;" :: "r"(s), "l"(gsrc));
}
__device__ __forceinline__ void cp_commit() {
    asm volatile("cp.async.commit_group;");
}
template <int N>
__device__ __forceinline__ void cp_wait() {
    asm volatile("cp.async.wait_group %0;" :: "n"(N));
}

// ---------------- mma helpers ----------------
__device__ __forceinline__ uint32_t smem_u32(const void* p) {
    uint32_t a;
    asm("{ .reg .u64 t; cvta.to.shared.u64 t, %1; cvt.u32.u64 %0, t; }" : "=r"(a) : "l"(p));
    return a;
}
__device__ __forceinline__ void ldsm4(uint32_t& r0, uint32_t& r1, uint32_t& r2, uint32_t& r3,
                                      uint32_t addr) {
    asm volatile("ldmatrix.sync.aligned.m8n8.x4.shared.b16 {%0,%1,%2,%3}, [%4];"
                 : "=r"(r0), "=r"(r1), "=r"(r2), "=r"(r3) : "r"(addr));
}
__device__ __forceinline__ void mma_f16(float* d, const uint32_t* a, uint32_t b0, uint32_t b1) {
    asm volatile(
        "mma.sync.aligned.m16n8k16.row.col.f32.f16.f16.f32 "
        "{%0,%1,%2,%3}, {%4,%5,%6,%7}, {%8,%9}, {%0,%1,%2,%3};"
        : "+f"(d[0]), "+f"(d[1]), "+f"(d[2]), "+f"(d[3])
        : "r"(a[0]), "r"(a[1]), "r"(a[2]), "r"(a[3]), "r"(b0), "r"(b1));
}

// ---------------- scratch ----------------
__device__ __half g_x_h[4 * 64 * 64 * 256];      // [b][h][w][c] fp16
__device__ int4   g_off4[4 * 9 * 64 * 64];       // corner elem offsets (half units)
__device__ uint4  g_cwh[4 * 9 * 64 * 64];        // 4 duplicated half2 corner weights
__device__ float  g_bias[256];
__device__ __align__(16) float2 g_dwp[9][128];   // [tap][ch-pair] depthwise weights
__device__ __half g_wh[256 * 256];               // [o][c] fp16 weights (BN folded)
__device__ __half g_mid[16384 * 256];            // [px][c] fp16 mid

// ---------------- kernel 1: NCHW fp32 -> NHWC fp16 ----------------
__global__ void k_transpose(const float* __restrict__ x) {
    __shared__ float tile[32][33];
    int b  = blockIdx.z;
    int s0 = blockIdx.x * 32;
    int c0 = blockIdx.y * 32;
    int tx = threadIdx.x, ty = threadIdx.y;  // (32, 8)
    const float* xb = x + (size_t)b * 256 * 4096;
    __half* ob = g_x_h + (size_t)b * 4096 * 256;
#pragma unroll
    for (int i = 0; i < 32; i += 8)
        tile[ty + i][tx] = xb[(c0 + ty + i) * 4096 + s0 + tx];
    __syncthreads();
    int tid = ty * 32 + tx;
#pragma unroll
    for (int j = 0; j < 2; j++) {
        int it = tid + j * 256;
        int r  = it >> 4, pc = it & 15;
        __half2 v = __floats2half2_rn(tile[pc * 2][r], tile[pc * 2 + 1][r]);
        *(__half2*)(ob + (size_t)(s0 + r) * 256 + c0 + pc * 2) = v;
    }
}

// ---------------- kernel 2: weight prep ----------------
__global__ void k_prep(const float* __restrict__ pw, const float* __restrict__ bg,
                       const float* __restrict__ bb, const float* __restrict__ bm,
                       const float* __restrict__ bv, const float* __restrict__ dw) {
    int idx = blockIdx.x * 256 + threadIdx.x;   // 65536 total
    int c = idx & 255;
    int o = idx >> 8;
    float s = bg[o] * rsqrtf(bv[o] + EPS);
    float w = __ldg(pw + o * 256 + c) * s;
    g_wh[o * 256 + c] = __float2half_rn(w);
    if (idx < 256) {
        float s2 = bg[idx] * rsqrtf(bv[idx] + EPS);
        g_bias[idx] = bb[idx] - bm[idx] * s2;
    }
    if (idx < 9 * 128) {
        int k  = idx / 128;
        int cp = idx & 127;
        g_dwp[k][cp] = make_float2(__ldg(dw + (2 * cp) * 9 + k),
                                   __ldg(dw + (2 * cp + 1) * 9 + k));
    }
}

// ---------------- kernel 3: offset conv + sampling params (4-way group split) ----------------
__global__ __launch_bounds__(256) void k_offset(const float* __restrict__ gf,
                         const float* __restrict__ offw,
                         const float* __restrict__ og, const float* __restrict__ obt,
                         const float* __restrict__ om, const float* __restrict__ ov) {
    __shared__ __align__(16) char sbuf[46080];
    float2 (*s_w2)[64][10] = (float2(*)[64][10])sbuf;
    float2 (*s_red)[64][9] = (float2(*)[64][9])sbuf;   // overlay after weights done

    int bh = blockIdx.x;
    int b = bh >> 6, h = bh & 63;
    int tid = threadIdx.x;
    int w  = tid & 63;
    int gs = tid >> 6;    // 0..3

    for (int i = tid; i < 9 * 64 * 9; i += 256) {
        int t = i % 9;
        int g = (i / 9) & 63;
        int k = i / 576;
        float wdy = offw[(2 * k) * 576 + g * 9 + t];
        float wdx = offw[(2 * k + 1) * 576 + g * 9 + t];
        s_w2[k][g][t] = make_float2(wdy, wdx);
    }
    __syncthreads();

    u64 acc[9];
#pragma unroll
    for (int k = 0; k < 9; k++) acc[k] = 0ull;

    const float* gfb = gf + (size_t)b * 64 * 64 * 64;
    int g0 = gs * 16;
    for (int gi = 0; gi < 16; gi++) {
        int g = g0 + gi;
        float a[9];
#pragma unroll
        for (int r = 0; r < 3; r++) {
            int hh = h + r - 1;
            bool hv = (unsigned)hh < 64u;
#pragma unroll
            for (int q = 0; q < 3; q++) {
                int ww = w + q - 1;
                bool wv2 = (unsigned)ww < 64u;
                a[r * 3 + q] = (hv && wv2) ? __ldg(gfb + (g * 64 + hh) * 64 + ww) : 0.f;
            }
        }
        u64 a2[9];
#pragma unroll
        for (int t = 0; t < 9; t++) a2[t] = pk2(a[t], a[t]);
#pragma unroll
        for (int k = 0; k < 9; k++) {
            const u64* wr = (const u64*)&s_w2[k][g][0];
            ulonglong2 w01 = *(const ulonglong2*)(wr + 0);
            ulonglong2 w23 = *(const ulonglong2*)(wr + 2);
            ulonglong2 w45 = *(const ulonglong2*)(wr + 4);
            ulonglong2 w67 = *(const ulonglong2*)(wr + 6);
            u64 w8 = wr[8];
            acc[k] = ffma2_(w01.x, a2[0], acc[k]);
            acc[k] = ffma2_(w01.y, a2[1], acc[k]);
            acc[k] = ffma2_(w23.x, a2[2], acc[k]);
            acc[k] = ffma2_(w23.y, a2[3], acc[k]);
            acc[k] = ffma2_(w45.x, a2[4], acc[k]);
            acc[k] = ffma2_(w45.y, a2[5], acc[k]);
            acc[k] = ffma2_(w67.x, a2[6], acc[k]);
            acc[k] = ffma2_(w67.y, a2[7], acc[k]);
            acc[k] = ffma2_(w8,    a2[8], acc[k]);
        }
    }

    __syncthreads();
#pragma unroll
    for (int k = 0; k < 9; k++) {
        float lo, hi;
        upk2(acc[k], lo, hi);
        s_red[gs][w][k] = make_float2(lo, hi);
    }
    __syncthreads();
    if (gs != 0) return;

#pragma unroll
    for (int k = 0; k < 9; k++) {
        float2 p0 = s_red[0][w][k];
        float2 p1 = s_red[1][w][k];
        float2 p2 = s_red[2][w][k];
        float2 p3 = s_red[3][w][k];
        float dyr = (p0.x + p1.x) + (p2.x + p3.x);
        float dxr = (p0.y + p1.y) + (p2.y + p3.y);

        int j0 = 2 * k, j1 = 2 * k + 1;
        float s0 = og[j0] * rsqrtf(ov[j0] + EPS);
        float s1 = og[j1] * rsqrtf(ov[j1] + EPS);
        float dy = fmaxf((dyr - om[j0]) * s0 + obt[j0], 0.f);
        float dx = fmaxf((dxr - om[j1]) * s1 + obt[j1], 0.f);
        float ky = (float)((k / 3) - 1) * 2.0f;   // DIL = 2
        float kx = (float)((k % 3) - 1) * 2.0f;
        float gy = (float)h + ky + dy;
        float gx = (float)w + kx + dx;
        float y0f = floorf(gy), x0f = floorf(gx);
        float wy = gy - y0f, wx = gx - x0f;
        float omwy = 1.f - wy, omwx = 1.f - wx;
        int y0 = (int)y0f, x0 = (int)x0f;
        bool yv0 = (unsigned)y0 < 64u;
        bool yv1 = (unsigned)(y0 + 1) < 64u;
        bool xv0 = (unsigned)x0 < 64u;
        bool xv1 = (unsigned)(x0 + 1) < 64u;
        int y0c = min(max(y0, 0), 63);
        int y1c = min(max(y0 + 1, 0), 63);
        int x0c = min(max(x0, 0), 63);
        int x1c = min(max(x0 + 1, 0), 63);
        int idx = ((b * 9 + k) * 64 + h) * 64 + w;
        g_off4[idx] = make_int4((y0c * 64 + x0c) * 256, (y0c * 64 + x1c) * 256,
                                (y1c * 64 + x0c) * 256, (y1c * 64 + x1c) * 256);
        float c00 = omwy * omwx * (float)(yv0 && xv0);
        float c01 = omwy * wx   * (float)(yv0 && xv1);
        float c10 = wy * omwx   * (float)(yv1 && xv0);
        float c11 = wy * wx     * (float)(yv1 && xv1);
        __half2 h00 = __float2half2_rn(c00);
        __half2 h01 = __float2half2_rn(c01);
        __half2 h10 = __float2half2_rn(c10);
        __half2 h11 = __float2half2_rn(c11);
        uint4 pack;
        memcpy(&pack.x, &h00, 4);
        memcpy(&pack.y, &h01, 4);
        memcpy(&pack.z, &h10, 4);
        memcpy(&pack.w, &h11, 4);
        g_cwh[idx] = pack;
    }
}

// ---------------- kernel 4: fp16 sample + depthwise (half: grid 512) ----------------
__global__ __launch_bounds__(256, 3) void k_sample(int t0) {
    __shared__ __align__(16) int4 s_off[9][16];
    __shared__ __align__(16) uint4 s_cwh[9][16];

    int t  = t0 + blockIdx.x;     // global tile 0..1023
    int w0 = (t & 3) << 4;
    int h  = (t >> 2) & 63;
    int b  = t >> 8;
    int tid = threadIdx.x;

    if (tid < 144) {
        int k = tid / 16, p = tid & 15;
        int idx = ((b * 9 + k) * 64 + h) * 64 + w0 + p;
        s_off[k][p] = g_off4[idx];
        s_cwh[k][p] = g_cwh[idx];
    }

    int cg = tid & 31;        // lane: 8 channels, c = cg*8
    int ps = tid >> 5;        // warp id: pixels ps*2, ps*2+1
    int c  = cg << 3;
    __syncthreads();

    const __half* xh = g_x_h + (size_t)b * 4096 * 256 + c;
    int pgbase = b * 4096 + h * 64 + w0;

    u64 acc[2][4];
#pragma unroll
    for (int i = 0; i < 2; i++)
#pragma unroll
        for (int j = 0; j < 4; j++) acc[i][j] = 0ull;

#pragma unroll
    for (int k = 0; k < 9; k++) {
        ulonglong2 dwA = *(const ulonglong2*)&g_dwp[k][cg * 4];
        ulonglong2 dwB = *(const ulonglong2*)&g_dwp[k][cg * 4 + 2];
#pragma unroll
        for (int i = 0; i < 2; i++) {
            int p = ps * 2 + i;
            int4 o4 = s_off[k][p];
            uint4 r00 = __ldg((const uint4*)(xh + o4.x));
            uint4 r01 = __ldg((const uint4*)(xh + o4.y));
            uint4 r10 = __ldg((const uint4*)(xh + o4.z));
            uint4 r11 = __ldg((const uint4*)(xh + o4.w));
            uint4 cw = s_cwh[k][p];
            __half2 w00 = u2h(cw.x), w01 = u2h(cw.y), w10 = u2h(cw.z), w11 = u2h(cw.w);
            __half2 v0 = __hmul2(w00, u2h(r00.x));
            __half2 v1 = __hmul2(w00, u2h(r00.y));
            __half2 v2 = __hmul2(w00, u2h(r00.z));
            __half2 v3 = __hmul2(w00, u2h(r00.w));
            v0 = __hfma2(w01, u2h(r01.x), v0);
            v1 = __hfma2(w01, u2h(r01.y), v1);
            v2 = __hfma2(w01, u2h(r01.z), v2);
            v3 = __hfma2(w01, u2h(r01.w), v3);
            v0 = __hfma2(w10, u2h(r10.x), v0);
            v1 = __hfma2(w10, u2h(r10.y), v1);
            v2 = __hfma2(w10, u2h(r10.z), v2);
            v3 = __hfma2(w10, u2h(r10.w), v3);
            v0 = __hfma2(w11, u2h(r11.x), v0);
            v1 = __hfma2(w11, u2h(r11.y), v1);
            v2 = __hfma2(w11, u2h(r11.z), v2);
            v3 = __hfma2(w11, u2h(r11.w), v3);
            float2 f0 = __half22float2(v0);
            float2 f1 = __half22float2(v1);
            float2 f2 = __half22float2(v2);
            float2 f3 = __half22float2(v3);
            acc[i][0] = ffma2_(dwA.x, pk2(f0.x, f0.y), acc[i][0]);
            acc[i][1] = ffma2_(dwA.y, pk2(f1.x, f1.y), acc[i][1]);
            acc[i][2] = ffma2_(dwB.x, pk2(f2.x, f2.y), acc[i][2]);
            acc[i][3] = ffma2_(dwB.y, pk2(f3.x, f3.y), acc[i][3]);
        }
    }

#pragma unroll
    for (int i = 0; i < 2; i++) {
        int p = ps * 2 + i;
        float a0, a1, a2, a3, a4, a5, a6, a7;
        upk2(acc[i][0], a0, a1);
        upk2(acc[i][1], a2, a3);
        upk2(acc[i][2], a4, a5);
        upk2(acc[i][3], a6, a7);
        __half2 m0 = __floats2half2_rn(a0, a1);
        __half2 m1 = __floats2half2_rn(a2, a3);
        __half2 m2 = __floats2half2_rn(a4, a5);
        __half2 m3 = __floats2half2_rn(a6, a7);
        uint4 mv;
        memcpy(&mv.x, &m0, 4);
        memcpy(&mv.y, &m1, 4);
        memcpy(&mv.z, &m2, 4);
        memcpy(&mv.w, &m3, 4);
        *(uint4*)(g_mid + (size_t)(pgbase + p) * 256 + c) = mv;
    }
}

// ---------------- kernel 5: fp16 GEMM, 4-stage cp.async ring (half: grid 64 x 2) ----------------
#define ROWB   80
#define STAGEB 20480         // W (10240) + M (10240) per stage
#define M_OFF  10240
__global__ __launch_bounds__(256, 2) void k_gemm_mma(float* __restrict__ out, int pb0) {
    extern __shared__ __align__(1024) char dyn[];
    const int tid  = threadIdx.x;
    const int warp = tid >> 5, lane = tid & 31;
    const int wo   = warp >> 2;      // 0..1  (o dim)
    const int wp   = warp & 3;       // 0..3  (px dim)
    const int pb   = pb0 + blockIdx.x, ob = blockIdx.y;

    const uint32_t uS = smem_u32(dyn);

    float acc[4][4][4];
#pragma unroll
    for (int mt = 0; mt < 4; mt++)
#pragma unroll
        for (int nt = 0; nt < 4; nt++)
#pragma unroll
            for (int j = 0; j < 4; j++) acc[mt][nt][j] = 0.f;

    const int g  = lane >> 3, rr = lane & 7;
    const int lmo = ((g & 1) * 8 + rr) * ROWB + (g >> 1) * 16;

    auto ldchunk = [&](int ch, int st) {
        char* base = dyn + st * STAGEB;
#pragma unroll
        for (int i = 0; i < 2; i++) {
            int idx = tid + i * 256;
            int r = idx >> 2, kc8 = (idx & 3) * 8;
            cp16(base + r * ROWB + kc8 * 2,
                 g_wh + (size_t)(ob * 128 + r) * 256 + ch * 32 + kc8);
        }
#pragma unroll
        for (int i = 0; i < 2; i++) {
            int idx = tid + i * 256;
            int r = idx >> 2, kc8 = (idx & 3) * 8;
            cp16(base + M_OFF + r * ROWB + kc8 * 2,
                 g_mid + (size_t)(pb * 128 + r) * 256 + ch * 32 + kc8);
        }
    };

    // prefetch 3 stages
    ldchunk(0, 0); cp_commit();
    ldchunk(1, 1); cp_commit();
    ldchunk(2, 2); cp_commit();

#pragma unroll 1
    for (int ch = 0; ch < 8; ch++) {
        int st = ch & 3;
        if (ch < 6)      cp_wait<2>();
        else if (ch == 6) cp_wait<1>();
        else              cp_wait<0>();
        __syncthreads();                 // also orders prev-chunk reads vs +3 refill
        if (ch + 3 < 8) {
            ldchunk(ch + 3, (ch + 3) & 3);
            cp_commit();
        }

        uint32_t wbase = uS + st * STAGEB + (wo * 64) * ROWB + lmo;
        uint32_t bbase = uS + st * STAGEB + M_OFF + (wp * 32) * ROWB + lmo;

#pragma unroll
        for (int ks = 0; ks < 2; ks++) {
            int kb = ks * 32;
            uint32_t bm_[8];
            ldsm4(bm_[0], bm_[1], bm_[2], bm_[3], bbase + kb);
            ldsm4(bm_[4], bm_[5], bm_[6], bm_[7], bbase + 16 * ROWB + kb);
#pragma unroll
            for (int mt = 0; mt < 4; mt++) {
                uint32_t ah[4];
                uint32_t abase = wbase + mt * 16 * ROWB + kb;
                ldsm4(ah[0], ah[1], ah[2], ah[3], abase);
#pragma unroll
                for (int nt = 0; nt < 4; nt++) {
                    uint32_t b0 = bm_[(nt & 1) + (nt >> 1) * 4];
                    uint32_t b1 = bm_[(nt & 1) + (nt >> 1) * 4 + 2];
                    mma_f16(acc[mt][nt], ah, b0, b1);
                }
            }
        }
    }

    int pxg = pb * 128;
    int bidx = pxg >> 12;
    int hw0  = pxg & 4095;
    float* obase = out + (size_t)bidx * 1048576;
    int o_w  = ob * 128 + wo * 64;
    int px_w = hw0 + wp * 32;
#pragma unroll
    for (int mt = 0; mt < 4; mt++) {
        int r0 = o_w + mt * 16 + (lane >> 2);
        float bias0 = __ldg(g_bias + r0);
        float bias1 = __ldg(g_bias + r0 + 8);
        float* row0 = obase + (size_t)r0 * 4096;
        float* row1 = row0 + 8 * 4096;
#pragma unroll
        for (int nt = 0; nt < 4; nt++) {
            int px = px_w + nt * 8 + (lane & 3) * 2;
            float2 v0 = make_float2(fmaxf(acc[mt][nt][0] + bias0, 0.f),
                                    fmaxf(acc[mt][nt][1] + bias0, 0.f));
            float2 v1 = make_float2(fmaxf(acc[mt][nt][2] + bias1, 0.f),
                                    fmaxf(acc[mt][nt][3] + bias1, 0.f));
            *(float2*)(row0 + px) = v0;
            *(float2*)(row1 + px) = v1;
        }
    }
}

// ---------------- launch ----------------
extern "C" void kernel_launch(void* const* d_in, const int* in_sizes, int n_in,
                              void* d_out, int out_size) {
    const float* x    = (const float*)d_in[0];
    const float* gf   = (const float*)d_in[1];
    const float* offw = (const float*)d_in[2];
    const float* og   = (const float*)d_in[3];
    const float* obt  = (const float*)d_in[4];
    const float* om   = (const float*)d_in[5];
    const float* ov   = (const float*)d_in[6];
    const float* dww  = (const float*)d_in[7];
    const float* pww  = (const float*)d_in[8];
    const float* bg   = (const float*)d_in[9];
    const float* bb   = (const float*)d_in[10];
    const float* bm   = (const float*)d_in[11];
    const float* bv   = (const float*)d_in[12];
    float* out = (float*)d_out;

    static bool init = false;
    static cudaStream_t s1;
    static cudaEvent_t e0, e2, ev0, ev1;
    if (!init) {
        cudaFuncSetAttribute(k_gemm_mma, cudaFuncAttributeMaxDynamicSharedMemorySize, 81920);
        cudaStreamCreateWithFlags(&s1, cudaStreamNonBlocking);
        cudaEventCreateWithFlags(&e0, cudaEventDisableTiming);
        cudaEventCreateWithFlags(&e2, cudaEventDisableTiming);
        cudaEventCreateWithFlags(&ev0, cudaEventDisableTiming);
        cudaEventCreateWithFlags(&ev1, cudaEventDisableTiming);
        init = true;
    }

    // fork: transpose on side stream; prep+offset on main
    cudaEventRecord(e0, 0);
    cudaStreamWaitEvent(s1, e0, 0);
    k_transpose<<<dim3(128, 8, 4), dim3(32, 8), 0, s1>>>(x);

    k_prep<<<256, 256>>>(pww, bg, bb, bm, bv, dww);
    k_offset<<<256, 256>>>(gf, offw, og, obt, om, ov);
    cudaEventRecord(e2, 0);
    cudaStreamWaitEvent(s1, e2, 0);

    // 2-half pipeline: sample halves on s1, gemm halves on main
    k_sample<<<512, 256, 0, s1>>>(0);
    cudaEventRecord(ev0, s1);
    k_sample<<<512, 256, 0, s1>>>(512);
    cudaEventRecord(ev1, s1);

    cudaStreamWaitEvent(0, ev0, 0);
    k_gemm_mma<<<dim3(64, 2), 256, 81920>>>(out, 0);
    cudaStreamWaitEvent(0, ev1, 0);
    k_gemm_mma<<<dim3(64, 2), 256, 81920>>>(out, 64);
}

// round 15
// speedup vs baseline: 1.4063x; 1.0317x over previous
#include <cuda_runtime.h>
#include <cuda_bf16.h>
#include <cuda_fp16.h>
#include <cstdint>
#include <cstring>

#define EPS 1e-5f
typedef unsigned long long u64;

// ---------------- f32x2 packed helpers ----------------
__device__ __forceinline__ u64 pk2(float lo, float hi) {
    u64 r;
    asm("mov.b64 %0, {%1, %2};" : "=l"(r) : "f"(lo), "f"(hi));
    return r;
}
__device__ __forceinline__ void upk2(u64 v, float& lo, float& hi) {
    asm("mov.b64 {%0, %1}, %2;" : "=f"(lo), "=f"(hi) : "l"(v));
}
__device__ __forceinline__ u64 ffma2_(u64 a, u64 b, u64 c) {
    u64 d;
    asm("fma.rn.f32x2 %0, %1, %2, %3;" : "=l"(d) : "l"(a), "l"(b), "l"(c));
    return d;
}
__device__ __forceinline__ __half2 u2h(uint32_t u) {
    __half2 h;
    memcpy(&h, &u, 4);
    return h;
}

// ---------------- cp.async helpers ----------------
__device__ __forceinline__ void cp16(void* smem_dst, const void* gsrc) {
    unsigned s = (unsigned)__cvta_generic_to_shared(smem_dst);
    asm volatile("cp.async.cg.shared.global [%0], [%1], 16;" :: "r"(s), "l"(gsrc));
}
__device__ __forceinline__ void cp_commit() {
    asm volatile("cp.async.commit_group;");
}
template <int N>
__device__ __forceinline__ void cp_wait() {
    asm volatile("cp.async.wait_group %0;" :: "n"(N));
}

// ---------------- mma helpers ----------------
__device__ __forceinline__ uint32_t smem_u32(const void* p) {
    uint32_t a;
    asm("{ .reg .u64 t; cvta.to.shared.u64 t, %1; cvt.u32.u64 %0, t; }" : "=r"(a) : "l"(p));
    return a;
}
__device__ __forceinline__ void ldsm4(uint32_t& r0, uint32_t& r1, uint32_t& r2, uint32_t& r3,
                                      uint32_t addr) {
    asm volatile("ldmatrix.sync.aligned.m8n8.x4.shared.b16 {%0,%1,%2,%3}, [%4];"
                 : "=r"(r0), "=r"(r1), "=r"(r2), "=r"(r3) : "r"(addr));
}
__device__ __forceinline__ void mma_f16(float* d, const uint32_t* a, uint32_t b0, uint32_t b1) {
    asm volatile(
        "mma.sync.aligned.m16n8k16.row.col.f32.f16.f16.f32 "
        "{%0,%1,%2,%3}, {%4,%5,%6,%7}, {%8,%9}, {%0,%1,%2,%3};"
        : "+f"(d[0]), "+f"(d[1]), "+f"(d[2]), "+f"(d[3])
        : "r"(a[0]), "r"(a[1]), "r"(a[2]), "r"(a[3]), "r"(b0), "r"(b1));
}

// ---------------- scratch ----------------
__device__ __half g_x_h[4 * 64 * 64 * 256];      // [b][h][w][c] fp16
__device__ int4   g_off4[4 * 9 * 64 * 64];       // corner elem offsets (half units)
__device__ uint4  g_cwh[4 * 9 * 64 * 64];        // 4 duplicated half2 corner weights
__device__ float  g_bias[256];
__device__ __align__(16) float2 g_dwp[9][128];   // [tap][ch-pair] depthwise weights
__device__ __half g_wh[256 * 256];               // [o][c] fp16 weights (BN folded)
__device__ __half g_mid[16384 * 256];            // [px][c] fp16 mid

// ---------------- kernel 1: NCHW fp32 -> NHWC fp16 ----------------
__global__ void k_transpose(const float* __restrict__ x) {
    __shared__ float tile[32][33];
    int b  = blockIdx.z;
    int s0 = blockIdx.x * 32;
    int c0 = blockIdx.y * 32;
    int tx = threadIdx.x, ty = threadIdx.y;  // (32, 8)
    const float* xb = x + (size_t)b * 256 * 4096;
    __half* ob = g_x_h + (size_t)b * 4096 * 256;
#pragma unroll
    for (int i = 0; i < 32; i += 8)
        tile[ty + i][tx] = xb[(c0 + ty + i) * 4096 + s0 + tx];
    __syncthreads();
    int tid = ty * 32 + tx;
#pragma unroll
    for (int j = 0; j < 2; j++) {
        int it = tid + j * 256;
        int r  = it >> 4, pc = it & 15;
        __half2 v = __floats2half2_rn(tile[pc * 2][r], tile[pc * 2 + 1][r]);
        *(__half2*)(ob + (size_t)(s0 + r) * 256 + c0 + pc * 2) = v;
    }
}

// ---------------- kernel 2: weight prep ----------------
__global__ void k_prep(const float* __restrict__ pw, const float* __restrict__ bg,
                       const float* __restrict__ bb, const float* __restrict__ bm,
                       const float* __restrict__ bv, const float* __restrict__ dw) {
    int idx = blockIdx.x * 256 + threadIdx.x;   // 65536 total
    int c = idx & 255;
    int o = idx >> 8;
    float s = bg[o] * rsqrtf(bv[o] + EPS);
    float w = __ldg(pw + o * 256 + c) * s;
    g_wh[o * 256 + c] = __float2half_rn(w);
    if (idx < 256) {
        float s2 = bg[idx] * rsqrtf(bv[idx] + EPS);
        g_bias[idx] = bb[idx] - bm[idx] * s2;
    }
    if (idx < 9 * 128) {
        int k  = idx / 128;
        int cp = idx & 127;
        g_dwp[k][cp] = make_float2(__ldg(dw + (2 * cp) * 9 + k),
                                   __ldg(dw + (2 * cp + 1) * 9 + k));
    }
}

// ---------------- kernel 3: offset conv + sampling params (4-way group split) ----------------
__global__ __launch_bounds__(256) void k_offset(const float* __restrict__ gf,
                         const float* __restrict__ offw,
                         const float* __restrict__ og, const float* __restrict__ obt,
                         const float* __restrict__ om, const float* __restrict__ ov) {
    __shared__ __align__(16) char sbuf[46080];
    float2 (*s_w2)[64][10] = (float2(*)[64][10])sbuf;
    float2 (*s_red)[64][9] = (float2(*)[64][9])sbuf;   // overlay after weights done

    int bh = blockIdx.x;
    int b = bh >> 6, h = bh & 63;
    int tid = threadIdx.x;
    int w  = tid & 63;
    int gs = tid >> 6;    // 0..3

    for (int i = tid; i < 9 * 64 * 9; i += 256) {
        int t = i % 9;
        int g = (i / 9) & 63;
        int k = i / 576;
        float wdy = offw[(2 * k) * 576 + g * 9 + t];
        float wdx = offw[(2 * k + 1) * 576 + g * 9 + t];
        s_w2[k][g][t] = make_float2(wdy, wdx);
    }
    __syncthreads();

    u64 acc[9];
#pragma unroll
    for (int k = 0; k < 9; k++) acc[k] = 0ull;

    const float* gfb = gf + (size_t)b * 64 * 64 * 64;
    int g0 = gs * 16;
    for (int gi = 0; gi < 16; gi++) {
        int g = g0 + gi;
        float a[9];
#pragma unroll
        for (int r = 0; r < 3; r++) {
            int hh = h + r - 1;
            bool hv = (unsigned)hh < 64u;
#pragma unroll
            for (int q = 0; q < 3; q++) {
                int ww = w + q - 1;
                bool wv2 = (unsigned)ww < 64u;
                a[r * 3 + q] = (hv && wv2) ? __ldg(gfb + (g * 64 + hh) * 64 + ww) : 0.f;
            }
        }
        u64 a2[9];
#pragma unroll
        for (int t = 0; t < 9; t++) a2[t] = pk2(a[t], a[t]);
#pragma unroll
        for (int k = 0; k < 9; k++) {
            const u64* wr = (const u64*)&s_w2[k][g][0];
            ulonglong2 w01 = *(const ulonglong2*)(wr + 0);
            ulonglong2 w23 = *(const ulonglong2*)(wr + 2);
            ulonglong2 w45 = *(const ulonglong2*)(wr + 4);
            ulonglong2 w67 = *(const ulonglong2*)(wr + 6);
            u64 w8 = wr[8];
            acc[k] = ffma2_(w01.x, a2[0], acc[k]);
            acc[k] = ffma2_(w01.y, a2[1], acc[k]);
            acc[k] = ffma2_(w23.x, a2[2], acc[k]);
            acc[k] = ffma2_(w23.y, a2[3], acc[k]);
            acc[k] = ffma2_(w45.x, a2[4], acc[k]);
            acc[k] = ffma2_(w45.y, a2[5], acc[k]);
            acc[k] = ffma2_(w67.x, a2[6], acc[k]);
            acc[k] = ffma2_(w67.y, a2[7], acc[k]);
            acc[k] = ffma2_(w8,    a2[8], acc[k]);
        }
    }

    __syncthreads();
#pragma unroll
    for (int k = 0; k < 9; k++) {
        float lo, hi;
        upk2(acc[k], lo, hi);
        s_red[gs][w][k] = make_float2(lo, hi);
    }
    __syncthreads();
    if (gs != 0) return;

#pragma unroll
    for (int k = 0; k < 9; k++) {
        float2 p0 = s_red[0][w][k];
        float2 p1 = s_red[1][w][k];
        float2 p2 = s_red[2][w][k];
        float2 p3 = s_red[3][w][k];
        float dyr = (p0.x + p1.x) + (p2.x + p3.x);
        float dxr = (p0.y + p1.y) + (p2.y + p3.y);

        int j0 = 2 * k, j1 = 2 * k + 1;
        float s0 = og[j0] * rsqrtf(ov[j0] + EPS);
        float s1 = og[j1] * rsqrtf(ov[j1] + EPS);
        float dy = fmaxf((dyr - om[j0]) * s0 + obt[j0], 0.f);
        float dx = fmaxf((dxr - om[j1]) * s1 + obt[j1], 0.f);
        float ky = (float)((k / 3) - 1) * 2.0f;   // DIL = 2
        float kx = (float)((k % 3) - 1) * 2.0f;
        float gy = (float)h + ky + dy;
        float gx = (float)w + kx + dx;
        float y0f = floorf(gy), x0f = floorf(gx);
        float wy = gy - y0f, wx = gx - x0f;
        float omwy = 1.f - wy, omwx = 1.f - wx;
        int y0 = (int)y0f, x0 = (int)x0f;
        bool yv0 = (unsigned)y0 < 64u;
        bool yv1 = (unsigned)(y0 + 1) < 64u;
        bool xv0 = (unsigned)x0 < 64u;
        bool xv1 = (unsigned)(x0 + 1) < 64u;
        int y0c = min(max(y0, 0), 63);
        int y1c = min(max(y0 + 1, 0), 63);
        int x0c = min(max(x0, 0), 63);
        int x1c = min(max(x0 + 1, 0), 63);
        int idx = ((b * 9 + k) * 64 + h) * 64 + w;
        g_off4[idx] = make_int4((y0c * 64 + x0c) * 256, (y0c * 64 + x1c) * 256,
                                (y1c * 64 + x0c) * 256, (y1c * 64 + x1c) * 256);
        float c00 = omwy * omwx * (float)(yv0 && xv0);
        float c01 = omwy * wx   * (float)(yv0 && xv1);
        float c10 = wy * omwx   * (float)(yv1 && xv0);
        float c11 = wy * wx     * (float)(yv1 && xv1);
        __half2 h00 = __float2half2_rn(c00);
        __half2 h01 = __float2half2_rn(c01);
        __half2 h10 = __float2half2_rn(c10);
        __half2 h11 = __float2half2_rn(c11);
        uint4 pack;
        memcpy(&pack.x, &h00, 4);
        memcpy(&pack.y, &h01, 4);
        memcpy(&pack.z, &h10, 4);
        memcpy(&pack.w, &h11, 4);
        g_cwh[idx] = pack;
    }
}

// ---------------- kernel 4: fp16 sample + depthwise (half: grid 512) ----------------
__global__ __launch_bounds__(256, 3) void k_sample(int t0) {
    __shared__ __align__(16) int4 s_off[9][16];
    __shared__ __align__(16) uint4 s_cwh[9][16];

    int t  = t0 + blockIdx.x;     // global tile 0..1023
    int w0 = (t & 3) << 4;
    int h  = (t >> 2) & 63;
    int b  = t >> 8;
    int tid = threadIdx.x;

    if (tid < 144) {
        int k = tid / 16, p = tid & 15;
        int idx = ((b * 9 + k) * 64 + h) * 64 + w0 + p;
        s_off[k][p] = g_off4[idx];
        s_cwh[k][p] = g_cwh[idx];
    }

    int cg = tid & 31;        // lane: 8 channels, c = cg*8
    int ps = tid >> 5;        // warp id: pixels ps*2, ps*2+1
    int c  = cg << 3;
    __syncthreads();

    const __half* xh = g_x_h + (size_t)b * 4096 * 256 + c;
    int pgbase = b * 4096 + h * 64 + w0;

    u64 acc[2][4];
#pragma unroll
    for (int i = 0; i < 2; i++)
#pragma unroll
        for (int j = 0; j < 4; j++) acc[i][j] = 0ull;

#pragma unroll
    for (int k = 0; k < 9; k++) {
        ulonglong2 dwA = *(const ulonglong2*)&g_dwp[k][cg * 4];
        ulonglong2 dwB = *(const ulonglong2*)&g_dwp[k][cg * 4 + 2];
#pragma unroll
        for (int i = 0; i < 2; i++) {
            int p = ps * 2 + i;
            int4 o4 = s_off[k][p];
            uint4 r00 = __ldg((const uint4*)(xh + o4.x));
            uint4 r01 = __ldg((const uint4*)(xh + o4.y));
            uint4 r10 = __ldg((const uint4*)(xh + o4.z));
            uint4 r11 = __ldg((const uint4*)(xh + o4.w));
            uint4 cw = s_cwh[k][p];
            __half2 w00 = u2h(cw.x), w01 = u2h(cw.y), w10 = u2h(cw.z), w11 = u2h(cw.w);
            __half2 v0 = __hmul2(w00, u2h(r00.x));
            __half2 v1 = __hmul2(w00, u2h(r00.y));
            __half2 v2 = __hmul2(w00, u2h(r00.z));
            __half2 v3 = __hmul2(w00, u2h(r00.w));
            v0 = __hfma2(w01, u2h(r01.x), v0);
            v1 = __hfma2(w01, u2h(r01.y), v1);
            v2 = __hfma2(w01, u2h(r01.z), v2);
            v3 = __hfma2(w01, u2h(r01.w), v3);
            v0 = __hfma2(w10, u2h(r10.x), v0);
            v1 = __hfma2(w10, u2h(r10.y), v1);
            v2 = __hfma2(w10, u2h(r10.z), v2);
            v3 = __hfma2(w10, u2h(r10.w), v3);
            v0 = __hfma2(w11, u2h(r11.x), v0);
            v1 = __hfma2(w11, u2h(r11.y), v1);
            v2 = __hfma2(w11, u2h(r11.z), v2);
            v3 = __hfma2(w11, u2h(r11.w), v3);
            float2 f0 = __half22float2(v0);
            float2 f1 = __half22float2(v1);
            float2 f2 = __half22float2(v2);
            float2 f3 = __half22float2(v3);
            acc[i][0] = ffma2_(dwA.x, pk2(f0.x, f0.y), acc[i][0]);
            acc[i][1] = ffma2_(dwA.y, pk2(f1.x, f1.y), acc[i][1]);
            acc[i][2] = ffma2_(dwB.x, pk2(f2.x, f2.y), acc[i][2]);
            acc[i][3] = ffma2_(dwB.y, pk2(f3.x, f3.y), acc[i][3]);
        }
    }

#pragma unroll
    for (int i = 0; i < 2; i++) {
        int p = ps * 2 + i;
        float a0, a1, a2, a3, a4, a5, a6, a7;
        upk2(acc[i][0], a0, a1);
        upk2(acc[i][1], a2, a3);
        upk2(acc[i][2], a4, a5);
        upk2(acc[i][3], a6, a7);
        __half2 m0 = __floats2half2_rn(a0, a1);
        __half2 m1 = __floats2half2_rn(a2, a3);
        __half2 m2 = __floats2half2_rn(a4, a5);
        __half2 m3 = __floats2half2_rn(a6, a7);
        uint4 mv;
        memcpy(&mv.x, &m0, 4);
        memcpy(&mv.y, &m1, 4);
        memcpy(&mv.z, &m2, 4);
        memcpy(&mv.w, &m3, 4);
        *(uint4*)(g_mid + (size_t)(pgbase + p) * 256 + c) = mv;
    }
}

// ---------------- kernel 5: fp16 GEMM, 64o x 128px tiles, 4-stage ring ----------------
// grid per half: (64 px-tiles, 4 o-tiles) = 256 CTAs; 8 warps = (wo 2) x (wp 4), warp 32o x 32px
#define ROWB   80
#define W_SZ   5120          // 64 rows x 80 B
#define M_OFF  5120
#define STAGEB 15360         // W (5120) + M (10240)
__global__ __launch_bounds__(256, 3) void k_gemm_mma(float* __restrict__ out, int pb0) {
    extern __shared__ __align__(1024) char dyn[];
    const int tid  = threadIdx.x;
    const int warp = tid >> 5, lane = tid & 31;
    const int wo   = warp >> 2;      // 0..1  (o dim, 32 each)
    const int wp   = warp & 3;       // 0..3  (px dim, 32 each)
    const int pb   = pb0 + blockIdx.x, ob = blockIdx.y;   // ob: 0..3, 64 o each

    const uint32_t uS = smem_u32(dyn);

    float acc[2][4][4];
#pragma unroll
    for (int mt = 0; mt < 2; mt++)
#pragma unroll
        for (int nt = 0; nt < 4; nt++)
#pragma unroll
            for (int j = 0; j < 4; j++) acc[mt][nt][j] = 0.f;

    const int g  = lane >> 3, rr = lane & 7;
    const int lmo = ((g & 1) * 8 + rr) * ROWB + (g >> 1) * 16;

    auto ldchunk = [&](int ch, int st) {
        char* base = dyn + st * STAGEB;
        {
            int r = tid >> 2, kc8 = (tid & 3) * 8;   // 64 rows of W
            cp16(base + r * ROWB + kc8 * 2,
                 g_wh + (size_t)(ob * 64 + r) * 256 + ch * 32 + kc8);
        }
#pragma unroll
        for (int i = 0; i < 2; i++) {
            int idx = tid + i * 256;
            int r = idx >> 2, kc8 = (idx & 3) * 8;   // 128 rows of M
            cp16(base + M_OFF + r * ROWB + kc8 * 2,
                 g_mid + (size_t)(pb * 128 + r) * 256 + ch * 32 + kc8);
        }
    };

    // prefetch 3 stages
    ldchunk(0, 0); cp_commit();
    ldchunk(1, 1); cp_commit();
    ldchunk(2, 2); cp_commit();

#pragma unroll 1
    for (int ch = 0; ch < 8; ch++) {
        int st = ch & 3;
        if (ch < 6)      cp_wait<2>();
        else if (ch == 6) cp_wait<1>();
        else              cp_wait<0>();
        __syncthreads();
        if (ch + 3 < 8) {
            ldchunk(ch + 3, (ch + 3) & 3);
            cp_commit();
        }

        uint32_t wbase = uS + st * STAGEB + (wo * 32) * ROWB + lmo;
        uint32_t bbase = uS + st * STAGEB + M_OFF + (wp * 32) * ROWB + lmo;

#pragma unroll
        for (int ks = 0; ks < 2; ks++) {
            int kb = ks * 32;
            uint32_t bm_[8];
            ldsm4(bm_[0], bm_[1], bm_[2], bm_[3], bbase + kb);
            ldsm4(bm_[4], bm_[5], bm_[6], bm_[7], bbase + 16 * ROWB + kb);
#pragma unroll
            for (int mt = 0; mt < 2; mt++) {
                uint32_t ah[4];
                uint32_t abase = wbase + mt * 16 * ROWB + kb;
                ldsm4(ah[0], ah[1], ah[2], ah[3], abase);
#pragma unroll
                for (int nt = 0; nt < 4; nt++) {
                    uint32_t b0 = bm_[(nt & 1) + (nt >> 1) * 4];
                    uint32_t b1 = bm_[(nt & 1) + (nt >> 1) * 4 + 2];
                    mma_f16(acc[mt][nt], ah, b0, b1);
                }
            }
        }
    }

    int pxg = pb * 128;
    int bidx = pxg >> 12;
    int hw0  = pxg & 4095;
    float* obase = out + (size_t)bidx * 1048576;
    int o_w  = ob * 64 + wo * 32;
    int px_w = hw0 + wp * 32;
#pragma unroll
    for (int mt = 0; mt < 2; mt++) {
        int r0 = o_w + mt * 16 + (lane >> 2);
        float bias0 = __ldg(g_bias + r0);
        float bias1 = __ldg(g_bias + r0 + 8);
        float* row0 = obase + (size_t)r0 * 4096;
        float* row1 = row0 + 8 * 4096;
#pragma unroll
        for (int nt = 0; nt < 4; nt++) {
            int px = px_w + nt * 8 + (lane & 3) * 2;
            float2 v0 = make_float2(fmaxf(acc[mt][nt][0] + bias0, 0.f),
                                    fmaxf(acc[mt][nt][1] + bias0, 0.f));
            float2 v1 = make_float2(fmaxf(acc[mt][nt][2] + bias1, 0.f),
                                    fmaxf(acc[mt][nt][3] + bias1, 0.f));
            *(float2*)(row0 + px) = v0;
            *(float2*)(row1 + px) = v1;
        }
    }
}

// ---------------- launch ----------------
extern "C" void kernel_launch(void* const* d_in, const int* in_sizes, int n_in,
                              void* d_out, int out_size) {
    const float* x    = (const float*)d_in[0];
    const float* gf   = (const float*)d_in[1];
    const float* offw = (const float*)d_in[2];
    const float* og   = (const float*)d_in[3];
    const float* obt  = (const float*)d_in[4];
    const float* om   = (const float*)d_in[5];
    const float* ov   = (const float*)d_in[6];
    const float* dww  = (const float*)d_in[7];
    const float* pww  = (const float*)d_in[8];
    const float* bg   = (const float*)d_in[9];
    const float* bb   = (const float*)d_in[10];
    const float* bm   = (const float*)d_in[11];
    const float* bv   = (const float*)d_in[12];
    float* out = (float*)d_out;

    static bool init = false;
    static cudaStream_t s1;
    static cudaEvent_t e0, e2, ev0, ev1;
    if (!init) {
        cudaFuncSetAttribute(k_gemm_mma, cudaFuncAttributeMaxDynamicSharedMemorySize, 61440);
        cudaStreamCreateWithFlags(&s1, cudaStreamNonBlocking);
        cudaEventCreateWithFlags(&e0, cudaEventDisableTiming);
        cudaEventCreateWithFlags(&e2, cudaEventDisableTiming);
        cudaEventCreateWithFlags(&ev0, cudaEventDisableTiming);
        cudaEventCreateWithFlags(&ev1, cudaEventDisableTiming);
        init = true;
    }

    // fork: transpose on side stream; prep+offset on main
    cudaEventRecord(e0, 0);
    cudaStreamWaitEvent(s1, e0, 0);
    k_transpose<<<dim3(128, 8, 4), dim3(32, 8), 0, s1>>>(x);

    k_prep<<<256, 256>>>(pww, bg, bb, bm, bv, dww);
    k_offset<<<256, 256>>>(gf, offw, og, obt, om, ov);
    cudaEventRecord(e2, 0);
    cudaStreamWaitEvent(s1, e2, 0);

    // 2-half pipeline: sample halves on s1, gemm halves on main
    k_sample<<<512, 256, 0, s1>>>(0);
    cudaEventRecord(ev0, s1);
    k_sample<<<512, 256, 0, s1>>>(512);
    cudaEventRecord(ev1, s1);

    cudaStreamWaitEvent(0, ev0, 0);
    k_gemm_mma<<<dim3(64, 4), 256, 61440>>>(out, 0);
    cudaStreamWaitEvent(0, ev1, 0);
    k_gemm_mma<<<dim3(64, 4), 256, 61440>>>(out, 64);
}